// round 1
// baseline (speedup 1.0000x reference)
#include <cuda_runtime.h>
#include <math.h>

#define NATOMS  50000
#define NEDGE   1600000
#define NGRAPH  250
#define HDIM    64
#define NGAUSS  50
#define NB      3
#define MTAB    32768
#define TABMAX  8.6700f     // > 5*sqrt(3) = 8.66025
#define TABSCALE ((float)(MTAB - 1) / TABMAX)
#define TABSTEP  (TABMAX / (float)(MTAB - 1))

// ---------------- scratch (device globals; no allocation allowed) ----------
__device__ float g_d[NEDGE];                    // 6.4 MB  edge distances
__device__ float g_tab[NB * MTAB * HDIM];       // 25.2 MB Wf(d) lookup table
__device__ float g_h[NATOMS * HDIM];            // 12.8 MB node features
__device__ float g_hx[NATOMS * HDIM];           // 12.8 MB h @ cf1_w
__device__ float g_agg[NATOMS * HDIM];          // 12.8 MB scatter accumulator
__device__ float g_gr[NGRAPH * HDIM];           // graph readout

// shifted softplus
__device__ __forceinline__ float ssp(float v) {
    return fmaxf(v, 0.0f) + log1pf(expf(-fabsf(v))) - 0.6931471805599453f;
}

// ---------------- edge distances -------------------------------------------
__global__ void k_dist(const float* __restrict__ pos, const int* __restrict__ ei) {
    int e = blockIdx.x * blockDim.x + threadIdx.x;
    if (e >= NEDGE) return;
    int s = __ldg(ei + e);
    int t = __ldg(ei + NEDGE + e);
    float dx = __ldg(pos + 3 * t + 0) - __ldg(pos + 3 * s + 0);
    float dy = __ldg(pos + 3 * t + 1) - __ldg(pos + 3 * s + 1);
    float dz = __ldg(pos + 3 * t + 2) - __ldg(pos + 3 * s + 2);
    g_d[e] = sqrtf(dx * dx + dy * dy + dz * dz);
}

// ---------------- build Wf(d) table: [NB][MTAB][64] -------------------------
// Wf(d) = (ssp(rbf(d) @ W1 + b1) @ W2 + b2) * 0.5*(cos(d*pi/10)+1)
__global__ __launch_bounds__(64) void k_table(
    const float* __restrict__ w1, const float* __restrict__ b1,
    const float* __restrict__ w2, const float* __restrict__ b2)
{
    __shared__ float w1s[NGAUSS * 64];
    __shared__ float w2s[64 * 64];
    __shared__ float b1s[64], b2s[64];
    __shared__ float rbfs[NGAUSS];
    __shared__ float t1s[64];

    const int KPB = 32;
    int t  = blockIdx.x / (MTAB / KPB);
    int kb = blockIdx.x % (MTAB / KPB);
    int tid = threadIdx.x;

    for (int i = tid; i < NGAUSS * 64; i += 64) w1s[i] = w1[t * NGAUSS * 64 + i];
    for (int i = tid; i < 64 * 64;     i += 64) w2s[i] = w2[t * 64 * 64 + i];
    b1s[tid] = b1[t * 64 + tid];
    b2s[tid] = b2[t * 64 + tid];

    const float step  = 10.0f / 49.0f;
    const float coeff = -0.5f / (step * step);

    for (int kk = 0; kk < KPB; kk++) {
        int knot = kb * KPB + kk;
        float dv = (float)knot * TABSTEP;
        __syncthreads();                 // protect rbfs/t1s from previous iter
        if (tid < NGAUSS) {
            float dd = dv - (float)tid * step;
            rbfs[tid] = expf(coeff * dd * dd);
        }
        __syncthreads();
        float a = b1s[tid];
        #pragma unroll 10
        for (int j = 0; j < NGAUSS; j++) a += rbfs[j] * w1s[j * 64 + tid];
        t1s[tid] = ssp(a);
        __syncthreads();
        float a2 = b2s[tid];
        #pragma unroll 16
        for (int k = 0; k < 64; k++) a2 += t1s[k] * w2s[k * 64 + tid];
        float C = 0.5f * (cosf(dv * 0.31415926535897931f) + 1.0f);
        g_tab[((size_t)t * MTAB + knot) * 64 + tid] = a2 * C;
    }
}

// ---------------- embedding init + zero graph accumulator ------------------
__global__ void k_embed(const int* __restrict__ z, const float* __restrict__ emb) {
    int gid = blockIdx.x * blockDim.x + threadIdx.x;
    if (gid < NGRAPH * HDIM) g_gr[gid] = 0.0f;
    if (gid >= NATOMS * HDIM) return;
    int i = gid >> 6, f = gid & 63;
    g_h[gid] = __ldg(emb + __ldg(z + i) * HDIM + f);
}

// ---------------- hx = h @ cf1_w[t] ; agg = 0 -------------------------------
__global__ __launch_bounds__(256) void k_cf1(const float* __restrict__ W) {
    __shared__ float Ws[64 * 64];
    __shared__ float Xs[64 * 64];
    int r0 = blockIdx.x * 64;
    for (int i = threadIdx.x; i < 4096; i += 256) {
        Ws[i] = W[i];
        int r = i >> 6;
        Xs[i] = (r0 + r < NATOMS) ? g_h[(size_t)(r0 + r) * 64 + (i & 63)] : 0.0f;
    }
    __syncthreads();
    int row = threadIdx.x >> 2;
    int cg  = (threadIdx.x & 3) * 16;
    float acc[16];
    #pragma unroll
    for (int j = 0; j < 16; j++) acc[j] = 0.0f;
    #pragma unroll 16
    for (int k = 0; k < 64; k++) {
        float xv = Xs[row * 64 + k];
        #pragma unroll
        for (int j = 0; j < 16; j++) acc[j] += xv * Ws[k * 64 + cg + j];
    }
    int gr = r0 + row;
    if (gr < NATOMS) {
        #pragma unroll
        for (int j = 0; j < 16; j++) {
            g_hx[(size_t)gr * 64 + cg + j]  = acc[j];
            g_agg[(size_t)gr * 64 + cg + j] = 0.0f;
        }
    }
}

// ---------------- edge pass: msg = hx[src]*Wf(d); agg[dst] += msg ----------
// 16 lanes per edge, float4 per lane, vector reduction scatter.
__global__ __launch_bounds__(256) void k_edge(const int* __restrict__ ei, int t) {
    int gid = blockIdx.x * blockDim.x + threadIdx.x;
    int e = gid >> 4;
    if (e >= NEDGE) return;
    int lane = (gid & 15) * 4;

    int src = __ldg(ei + e);
    int dst = __ldg(ei + NEDGE + e);
    float d = g_d[e];

    float x = d * TABSCALE;
    int r0 = (int)x;
    r0 = max(0, min(r0, MTAB - 2));
    float w = x - (float)r0;

    const float* tb = g_tab + ((size_t)t * MTAB + r0) * 64 + lane;
    float4 a = *(const float4*)tb;
    float4 b = *(const float4*)(tb + 64);
    float4 hv = *(const float4*)(g_hx + (size_t)src * 64 + lane);

    float4 m;
    m.x = hv.x * (a.x + w * (b.x - a.x));
    m.y = hv.y * (a.y + w * (b.y - a.y));
    m.z = hv.z * (a.z + w * (b.z - a.z));
    m.w = hv.w * (a.w + w * (b.w - a.w));

    float* addr = g_agg + (size_t)dst * 64 + lane;
    asm volatile("red.global.add.v4.f32 [%0], {%1,%2,%3,%4};"
                 :: "l"(addr), "f"(m.x), "f"(m.y), "f"(m.z), "f"(m.w)
                 : "memory");
}

// ---------------- h += ssp(agg @ cf2_w + b) @ lin_w + lin_b ----------------
__global__ __launch_bounds__(256) void k_cf2lin(
    const float* __restrict__ W1, const float* __restrict__ B1,
    const float* __restrict__ W2, const float* __restrict__ B2)
{
    __shared__ float Ws[64 * 64];
    __shared__ float Xs[64 * 64];
    __shared__ float Us[64 * 64];
    int r0 = blockIdx.x * 64;
    for (int i = threadIdx.x; i < 4096; i += 256) {
        Ws[i] = W1[i];
        int r = i >> 6;
        Xs[i] = (r0 + r < NATOMS) ? g_agg[(size_t)(r0 + r) * 64 + (i & 63)] : 0.0f;
    }
    __syncthreads();
    int row = threadIdx.x >> 2;
    int cg  = (threadIdx.x & 3) * 16;
    float acc[16];
    #pragma unroll
    for (int j = 0; j < 16; j++) acc[j] = 0.0f;
    #pragma unroll 16
    for (int k = 0; k < 64; k++) {
        float xv = Xs[row * 64 + k];
        #pragma unroll
        for (int j = 0; j < 16; j++) acc[j] += xv * Ws[k * 64 + cg + j];
    }
    #pragma unroll
    for (int j = 0; j < 16; j++) Us[row * 64 + cg + j] = ssp(acc[j] + B1[cg + j]);
    __syncthreads();
    for (int i = threadIdx.x; i < 4096; i += 256) Ws[i] = W2[i];
    __syncthreads();
    #pragma unroll
    for (int j = 0; j < 16; j++) acc[j] = B2[cg + j];
    #pragma unroll 16
    for (int k = 0; k < 64; k++) {
        float uv = Us[row * 64 + k];
        #pragma unroll
        for (int j = 0; j < 16; j++) acc[j] += uv * Ws[k * 64 + cg + j];
    }
    int gr = r0 + row;
    if (gr < NATOMS) {
        #pragma unroll
        for (int j = 0; j < 16; j++)
            g_h[(size_t)gr * 64 + cg + j] += acc[j];
    }
}

// ---------------- graph readout scatter -------------------------------------
__global__ void k_scatter_g(const int* __restrict__ batch) {
    int gid = blockIdx.x * blockDim.x + threadIdx.x;
    int i = gid >> 4;
    if (i >= NATOMS) return;
    int lane = (gid & 15) * 4;
    int b = __ldg(batch + i);
    float4 v = *(const float4*)(g_h + (size_t)i * 64 + lane);
    float* addr = g_gr + (size_t)b * 64 + lane;
    asm volatile("red.global.add.v4.f32 [%0], {%1,%2,%3,%4};"
                 :: "l"(addr), "f"(v.x), "f"(v.y), "f"(v.z), "f"(v.w)
                 : "memory");
}

// ---------------- output head ------------------------------------------------
__global__ __launch_bounds__(256) void k_head(
    const float* __restrict__ W1, const float* __restrict__ B1,
    const float* __restrict__ W2, const float* __restrict__ B2,
    float* __restrict__ out)
{
    __shared__ float w1s[64 * 32];
    __shared__ float w2s[32];
    __shared__ float b1s[32];
    for (int i = threadIdx.x; i < 2048; i += 256) w1s[i] = W1[i];
    if (threadIdx.x < 32) { w2s[threadIdx.x] = W2[threadIdx.x]; b1s[threadIdx.x] = B1[threadIdx.x]; }
    __syncthreads();
    int g = threadIdx.x;
    if (g >= NGRAPH) return;
    float gv[64];
    #pragma unroll 16
    for (int k = 0; k < 64; k++) gv[k] = g_gr[g * 64 + k];
    float o = B2[0];
    #pragma unroll 4
    for (int j = 0; j < 32; j++) {
        float a = b1s[j];
        #pragma unroll 16
        for (int k = 0; k < 64; k++) a += gv[k] * w1s[k * 32 + j];
        o += fmaxf(a, 0.0f) * w2s[j];
    }
    out[g] = o;
}

// ---------------- launcher ---------------------------------------------------
extern "C" void kernel_launch(void* const* d_in, const int* in_sizes, int n_in,
                              void* d_out, int out_size) {
    const int*   z      = (const int*)  d_in[0];
    const float* pos    = (const float*)d_in[1];
    const int*   batch  = (const int*)  d_in[2];
    const int*   ei     = (const int*)  d_in[3];
    const float* emb    = (const float*)d_in[4];
    const float* mlp_w1 = (const float*)d_in[5];
    const float* mlp_b1 = (const float*)d_in[6];
    const float* mlp_w2 = (const float*)d_in[7];
    const float* mlp_b2 = (const float*)d_in[8];
    const float* cf1_w  = (const float*)d_in[9];
    const float* cf2_w  = (const float*)d_in[10];
    const float* cf2_b  = (const float*)d_in[11];
    const float* lin_w  = (const float*)d_in[12];
    const float* lin_b  = (const float*)d_in[13];
    const float* out1_w = (const float*)d_in[14];
    const float* out1_b = (const float*)d_in[15];
    const float* out2_w = (const float*)d_in[16];
    const float* out2_b = (const float*)d_in[17];
    float* out = (float*)d_out;

    k_dist <<<(NEDGE + 255) / 256, 256>>>(pos, ei);
    k_table<<<NB * (MTAB / 32), 64>>>(mlp_w1, mlp_b1, mlp_w2, mlp_b2);
    k_embed<<<(NATOMS * HDIM + 255) / 256, 256>>>(z, emb);

    for (int t = 0; t < NB; t++) {
        k_cf1   <<<(NATOMS + 63) / 64, 256>>>(cf1_w + (size_t)t * 64 * 64);
        k_edge  <<<(NEDGE * 16 + 255) / 256, 256>>>(ei, t);
        k_cf2lin<<<(NATOMS + 63) / 64, 256>>>(cf2_w + (size_t)t * 64 * 64,
                                              cf2_b + (size_t)t * 64,
                                              lin_w + (size_t)t * 64 * 64,
                                              lin_b + (size_t)t * 64);
    }

    k_scatter_g<<<(NATOMS * 16 + 255) / 256, 256>>>(batch);
    k_head<<<1, 256>>>(out1_w, out1_b, out2_w, out2_b, out);
}

// round 2
// speedup vs baseline: 1.3220x; 1.3220x over previous
#include <cuda_runtime.h>
#include <cuda_fp16.h>
#include <math.h>

#define NATOMS  50000
#define NEDGE   1600000
#define NGRAPH  250
#define HDIM    64
#define NGAUSS  50
#define NB      3
#define MTAB    8192
#define TABMAX  8.6700f     // > 5*sqrt(3) = 8.66025
#define TABSCALE ((float)(MTAB - 1) / TABMAX)
#define TABSTEP  (TABMAX / (float)(MTAB - 1))

// ---------------- scratch (device globals; no allocation allowed) ----------
__device__ __half g_tabh[NB * MTAB * HDIM];     // 3.1 MB  Wf(d) table, fp16
__device__ float  g_h[NATOMS * HDIM];           // 12.8 MB node features
__device__ __half g_hxh[NATOMS * HDIM];         // 6.4 MB  h @ cf1_w, fp16
__device__ float  g_agg[NATOMS * HDIM];         // 12.8 MB gather accumulator
__device__ float  g_gr[NGRAPH * HDIM];          // graph readout
__device__ int    g_cnt[NATOMS];                // histogram
__device__ int    g_rp[NATOMS + 1];             // CSR rowptr
__device__ int    g_cur[NATOMS];                // scatter cursors
__device__ uint2  g_srcx[NEDGE];                // sorted-by-dst (src, x) records

__device__ __forceinline__ float ssp(float v) {
    return fmaxf(v, 0.0f) + log1pf(expf(-fabsf(v))) - 0.6931471805599453f;
}

// ---------------- CSR build: hist -> scan -> scatter ------------------------
__global__ void k_zero() {
    int i = blockIdx.x * blockDim.x + threadIdx.x;
    if (i < NATOMS) g_cnt[i] = 0;
    if (i < NGRAPH * HDIM) g_gr[i] = 0.0f;
}

__global__ void k_hist(const int* __restrict__ ei) {
    int e = blockIdx.x * blockDim.x + threadIdx.x;
    if (e >= NEDGE) return;
    atomicAdd(&g_cnt[__ldg(ei + NEDGE + e)], 1);
}

// single-block exclusive scan over NATOMS counts (warp-shuffle based)
__global__ __launch_bounds__(1024) void k_scan() {
    __shared__ int wsum[32];
    __shared__ int s_carry;
    __shared__ int s_btot;
    int tid = threadIdx.x, lane = tid & 31, wid = tid >> 5;
    if (tid == 0) s_carry = 0;
    __syncthreads();
    for (int base = 0; base < NATOMS; base += 1024) {
        int i = base + tid;
        int v = (i < NATOMS) ? g_cnt[i] : 0;
        // warp inclusive scan
        int incl = v;
        #pragma unroll
        for (int off = 1; off < 32; off <<= 1) {
            int n = __shfl_up_sync(0xffffffffu, incl, off);
            if (lane >= off) incl += n;
        }
        if (lane == 31) wsum[wid] = incl;
        __syncthreads();
        if (wid == 0) {
            int wv = wsum[lane];
            int wincl = wv;
            #pragma unroll
            for (int off = 1; off < 32; off <<= 1) {
                int n = __shfl_up_sync(0xffffffffu, wincl, off);
                if (lane >= off) wincl += n;
            }
            wsum[lane] = wincl - wv;   // exclusive warp prefix
            if (lane == 31) s_btot = wincl;
        }
        __syncthreads();
        int excl = s_carry + wsum[wid] + incl - v;
        if (i < NATOMS) { g_rp[i] = excl; g_cur[i] = excl; }
        __syncthreads();
        if (tid == 0) s_carry += s_btot;
        __syncthreads();
    }
    if (tid == 0) g_rp[NATOMS] = NEDGE;
}

// compute distance + table coord, scatter (src, x) into dst-sorted order
__global__ void k_scatter(const float* __restrict__ pos, const int* __restrict__ ei) {
    int e = blockIdx.x * blockDim.x + threadIdx.x;
    if (e >= NEDGE) return;
    int s = __ldg(ei + e);
    int t = __ldg(ei + NEDGE + e);
    float dx = __ldg(pos + 3 * t + 0) - __ldg(pos + 3 * s + 0);
    float dy = __ldg(pos + 3 * t + 1) - __ldg(pos + 3 * s + 1);
    float dz = __ldg(pos + 3 * t + 2) - __ldg(pos + 3 * s + 2);
    float d = sqrtf(dx * dx + dy * dy + dz * dz);
    float x = fminf(d * TABSCALE, (float)(MTAB - 1) - 0.001f);
    int p = atomicAdd(&g_cur[t], 1);
    g_srcx[p] = make_uint2((unsigned)s, __float_as_uint(x));
}

// ---------------- build Wf(d) table (fp16): [NB][MTAB][64] ------------------
__global__ __launch_bounds__(64) void k_table(
    const float* __restrict__ w1, const float* __restrict__ b1,
    const float* __restrict__ w2, const float* __restrict__ b2)
{
    __shared__ float w1s[NGAUSS * 64];
    __shared__ float w2s[64 * 64];
    __shared__ float b1s[64], b2s[64];
    __shared__ float rbfs[NGAUSS];
    __shared__ float t1s[64];

    const int KPB = 32;
    int t  = blockIdx.x / (MTAB / KPB);
    int kb = blockIdx.x % (MTAB / KPB);
    int tid = threadIdx.x;

    for (int i = tid; i < NGAUSS * 64; i += 64) w1s[i] = w1[t * NGAUSS * 64 + i];
    for (int i = tid; i < 64 * 64;     i += 64) w2s[i] = w2[t * 64 * 64 + i];
    b1s[tid] = b1[t * 64 + tid];
    b2s[tid] = b2[t * 64 + tid];

    const float step  = 10.0f / 49.0f;
    const float coeff = -0.5f / (step * step);

    for (int kk = 0; kk < KPB; kk++) {
        int knot = kb * KPB + kk;
        float dv = (float)knot * TABSTEP;
        __syncthreads();
        if (tid < NGAUSS) {
            float dd = dv - (float)tid * step;
            rbfs[tid] = expf(coeff * dd * dd);
        }
        __syncthreads();
        float a = b1s[tid];
        #pragma unroll 10
        for (int j = 0; j < NGAUSS; j++) a += rbfs[j] * w1s[j * 64 + tid];
        t1s[tid] = ssp(a);
        __syncthreads();
        float a2 = b2s[tid];
        #pragma unroll 16
        for (int k = 0; k < 64; k++) a2 += t1s[k] * w2s[k * 64 + tid];
        float C = 0.5f * (cosf(dv * 0.31415926535897931f) + 1.0f);
        g_tabh[((size_t)t * MTAB + knot) * 64 + tid] = __float2half_rn(a2 * C);
    }
}

// ---------------- embedding init --------------------------------------------
__global__ void k_embed(const int* __restrict__ z, const float* __restrict__ emb) {
    int gid = blockIdx.x * blockDim.x + threadIdx.x;
    if (gid >= NATOMS * HDIM) return;
    int i = gid >> 6, f = gid & 63;
    g_h[gid] = __ldg(emb + __ldg(z + i) * HDIM + f);
}

// ---------------- hx = h @ cf1_w[t]  (fp16 out) ------------------------------
// 4 lanes per row; X row held in registers, broadcast via quad shuffles.
__global__ __launch_bounds__(256) void k_cf1(const float* __restrict__ W) {
    __shared__ float Ws[64 * 64];
    for (int i = threadIdx.x; i < 4096; i += 256) Ws[i] = W[i];
    __syncthreads();

    int row  = blockIdx.x * 64 + (threadIdx.x >> 2);
    int rowc = min(row, NATOMS - 1);
    int q    = threadIdx.x & 3;
    int lane = threadIdx.x & 31;

    float xs[16];
    const float4* xr = (const float4*)(g_h + (size_t)rowc * 64 + q * 16);
    ((float4*)xs)[0] = xr[0]; ((float4*)xs)[1] = xr[1];
    ((float4*)xs)[2] = xr[2]; ((float4*)xs)[3] = xr[3];

    float acc[16];
    #pragma unroll
    for (int j = 0; j < 16; j++) acc[j] = 0.0f;

    #pragma unroll
    for (int k = 0; k < 64; k++) {
        float xk = __shfl_sync(0xffffffffu, xs[k & 15], (lane & ~3) | (k >> 4), 32);
        const float* wr = Ws + k * 64 + q * 16;
        #pragma unroll
        for (int j = 0; j < 16; j++) acc[j] = fmaf(xk, wr[j], acc[j]);
    }

    if (row < NATOMS) {
        __half2 hp[8];
        #pragma unroll
        for (int j = 0; j < 8; j++) hp[j] = __floats2half2_rn(acc[2 * j], acc[2 * j + 1]);
        uint4* dstp = (uint4*)(g_hxh + (size_t)row * 64 + q * 16);
        dstp[0] = *(uint4*)(hp);
        dstp[1] = *(uint4*)(hp + 4);
    }
}

// ---------------- gather-aggregate: agg[n] = sum_e hx[src_e]*Wf(d_e) --------
// one warp per node; 2 features per lane; fp32 accumulation in registers
__global__ __launch_bounds__(256) void k_agg(int t) {
    int node = blockIdx.x * 8 + (threadIdx.x >> 5);
    if (node >= NATOMS) return;
    int lane = threadIdx.x & 31;
    int beg = g_rp[node], end = g_rp[node + 1];

    float a0 = 0.0f, a1 = 0.0f;
    const __half* tb = g_tabh + (size_t)t * MTAB * 64;

    for (int p = beg; p < end; p++) {
        uint2 rec = __ldg(&g_srcx[p]);
        float x = __uint_as_float(rec.y);
        int   r0 = (int)x;
        float w  = x - (float)r0;
        const __half2* ta = (const __half2*)(tb + (size_t)r0 * 64) + lane;
        float2 af = __half22float2(__ldg(ta));
        float2 bf = __half22float2(__ldg(ta + 32));
        float2 hf = __half22float2(__ldg((const __half2*)(g_hxh + (size_t)rec.x * 64) + lane));
        a0 = fmaf(hf.x, fmaf(w, bf.x - af.x, af.x), a0);
        a1 = fmaf(hf.y, fmaf(w, bf.y - af.y, af.y), a1);
    }
    ((float2*)g_agg)[(size_t)node * 32 + lane] = make_float2(a0, a1);
}

// ---------------- h += ssp(agg @ cf2_w + b1) @ lin_w + b2 -------------------
// fused two GEMMs; intermediate stays in registers (lane's slice == its X slice)
__global__ __launch_bounds__(256) void k_cf2lin(
    const float* __restrict__ W1, const float* __restrict__ B1,
    const float* __restrict__ W2, const float* __restrict__ B2)
{
    __shared__ float W1s[64 * 64];
    __shared__ float W2s[64 * 64];
    for (int i = threadIdx.x; i < 4096; i += 256) { W1s[i] = W1[i]; W2s[i] = W2[i]; }
    __syncthreads();

    int row  = blockIdx.x * 64 + (threadIdx.x >> 2);
    int rowc = min(row, NATOMS - 1);
    int q    = threadIdx.x & 3;
    int lane = threadIdx.x & 31;

    float xs[16];
    const float4* xr = (const float4*)(g_agg + (size_t)rowc * 64 + q * 16);
    ((float4*)xs)[0] = xr[0]; ((float4*)xs)[1] = xr[1];
    ((float4*)xs)[2] = xr[2]; ((float4*)xs)[3] = xr[3];

    float acc[16];
    #pragma unroll
    for (int j = 0; j < 16; j++) acc[j] = B1[q * 16 + j];

    #pragma unroll
    for (int k = 0; k < 64; k++) {
        float xk = __shfl_sync(0xffffffffu, xs[k & 15], (lane & ~3) | (k >> 4), 32);
        const float* wr = W1s + k * 64 + q * 16;
        #pragma unroll
        for (int j = 0; j < 16; j++) acc[j] = fmaf(xk, wr[j], acc[j]);
    }

    float us[16];
    #pragma unroll
    for (int j = 0; j < 16; j++) us[j] = ssp(acc[j]);

    #pragma unroll
    for (int j = 0; j < 16; j++) acc[j] = B2[q * 16 + j];

    #pragma unroll
    for (int k = 0; k < 64; k++) {
        float uk = __shfl_sync(0xffffffffu, us[k & 15], (lane & ~3) | (k >> 4), 32);
        const float* wr = W2s + k * 64 + q * 16;
        #pragma unroll
        for (int j = 0; j < 16; j++) acc[j] = fmaf(uk, wr[j], acc[j]);
    }

    if (row < NATOMS) {
        float* hp = g_h + (size_t)row * 64 + q * 16;
        #pragma unroll
        for (int j = 0; j < 16; j++) hp[j] += acc[j];
    }
}

// ---------------- graph readout scatter --------------------------------------
__global__ void k_scatter_g(const int* __restrict__ batch) {
    int gid = blockIdx.x * blockDim.x + threadIdx.x;
    int i = gid >> 4;
    if (i >= NATOMS) return;
    int lane = (gid & 15) * 4;
    int b = __ldg(batch + i);
    float4 v = *(const float4*)(g_h + (size_t)i * 64 + lane);
    float* addr = g_gr + (size_t)b * 64 + lane;
    asm volatile("red.global.add.v4.f32 [%0], {%1,%2,%3,%4};"
                 :: "l"(addr), "f"(v.x), "f"(v.y), "f"(v.z), "f"(v.w)
                 : "memory");
}

// ---------------- output head -------------------------------------------------
__global__ __launch_bounds__(256) void k_head(
    const float* __restrict__ W1, const float* __restrict__ B1,
    const float* __restrict__ W2, const float* __restrict__ B2,
    float* __restrict__ out)
{
    __shared__ float w1s[64 * 32];
    __shared__ float w2s[32];
    __shared__ float b1s[32];
    for (int i = threadIdx.x; i < 2048; i += 256) w1s[i] = W1[i];
    if (threadIdx.x < 32) { w2s[threadIdx.x] = W2[threadIdx.x]; b1s[threadIdx.x] = B1[threadIdx.x]; }
    __syncthreads();
    int g = threadIdx.x;
    if (g >= NGRAPH) return;
    float gv[64];
    #pragma unroll 16
    for (int k = 0; k < 64; k++) gv[k] = g_gr[g * 64 + k];
    float o = B2[0];
    #pragma unroll 4
    for (int j = 0; j < 32; j++) {
        float a = b1s[j];
        #pragma unroll 16
        for (int k = 0; k < 64; k++) a += gv[k] * w1s[k * 32 + j];
        o += fmaxf(a, 0.0f) * w2s[j];
    }
    out[g] = o;
}

// ---------------- launcher -----------------------------------------------------
extern "C" void kernel_launch(void* const* d_in, const int* in_sizes, int n_in,
                              void* d_out, int out_size) {
    const int*   z      = (const int*)  d_in[0];
    const float* pos    = (const float*)d_in[1];
    const int*   batch  = (const int*)  d_in[2];
    const int*   ei     = (const int*)  d_in[3];
    const float* emb    = (const float*)d_in[4];
    const float* mlp_w1 = (const float*)d_in[5];
    const float* mlp_b1 = (const float*)d_in[6];
    const float* mlp_w2 = (const float*)d_in[7];
    const float* mlp_b2 = (const float*)d_in[8];
    const float* cf1_w  = (const float*)d_in[9];
    const float* cf2_w  = (const float*)d_in[10];
    const float* cf2_b  = (const float*)d_in[11];
    const float* lin_w  = (const float*)d_in[12];
    const float* lin_b  = (const float*)d_in[13];
    const float* out1_w = (const float*)d_in[14];
    const float* out1_b = (const float*)d_in[15];
    const float* out2_w = (const float*)d_in[16];
    const float* out2_b = (const float*)d_in[17];
    float* out = (float*)d_out;

    // CSR build (edge_index constant across interactions)
    k_zero   <<<(NATOMS + 255) / 256, 256>>>();
    k_hist   <<<(NEDGE + 255) / 256, 256>>>(ei);
    k_scan   <<<1, 1024>>>();
    k_scatter<<<(NEDGE + 255) / 256, 256>>>(pos, ei);

    k_table<<<NB * (MTAB / 32), 64>>>(mlp_w1, mlp_b1, mlp_w2, mlp_b2);
    k_embed<<<(NATOMS * HDIM + 255) / 256, 256>>>(z, emb);

    for (int t = 0; t < NB; t++) {
        k_cf1   <<<(NATOMS + 63) / 64, 256>>>(cf1_w + (size_t)t * 64 * 64);
        k_agg   <<<(NATOMS + 7) / 8, 256>>>(t);
        k_cf2lin<<<(NATOMS + 63) / 64, 256>>>(cf2_w + (size_t)t * 64 * 64,
                                              cf2_b + (size_t)t * 64,
                                              lin_w + (size_t)t * 64 * 64,
                                              lin_b + (size_t)t * 64);
    }

    k_scatter_g<<<(NATOMS * 16 + 255) / 256, 256>>>(batch);
    k_head<<<1, 256>>>(out1_w, out1_b, out2_w, out2_b, out);
}

// round 3
// speedup vs baseline: 1.4434x; 1.0919x over previous
#include <cuda_runtime.h>
#include <cuda_fp16.h>
#include <math.h>

#define NATOMS  50000
#define NEDGE   1600000
#define NGRAPH  250
#define HDIM    64
#define NGAUSS  50
#define NB      3
#define MTAB    8192
#define TABMAX  8.6700f     // > 5*sqrt(3) = 8.66025
#define TABSCALE ((float)(MTAB - 1) / TABMAX)
#define TABSTEP  (TABMAX / (float)(MTAB - 1))
#define NSCANB  49          // ceil(NATOMS / 1024)

// ---------------- scratch (device globals; no allocation allowed) ----------
__device__ __half g_tabh[NB * MTAB * HDIM];     // 3.1 MB  Wf(d) table, fp16
__device__ float  g_h[NATOMS * HDIM];           // 12.8 MB node features
__device__ __half g_hxh[NATOMS * HDIM];         // 6.4 MB  h @ cf1_w, fp16
__device__ float  g_agg[NATOMS * HDIM];         // 12.8 MB gather accumulator
__device__ float  g_gr[NGRAPH * HDIM];          // graph readout
__device__ int    g_cnt[NATOMS];                // histogram
__device__ int    g_rp[NATOMS + 1];             // CSR rowptr
__device__ int    g_cur[NATOMS];                // scatter cursors
__device__ int    g_bsum[64];                   // scan block sums
__device__ uint2  g_srcx[NEDGE];                // dst-sorted (src, x) records

__device__ __forceinline__ float ssp(float v) {
    return fmaxf(v, 0.0f) + log1pf(expf(-fabsf(v))) - 0.6931471805599453f;
}

// ---------------- CSR build --------------------------------------------------
__global__ void k_zero() {
    int i = blockIdx.x * blockDim.x + threadIdx.x;
    if (i < NATOMS) g_cnt[i] = 0;
    if (i < NGRAPH * HDIM) g_gr[i] = 0.0f;
}

__global__ void k_hist(const int* __restrict__ ei) {
    int e = blockIdx.x * blockDim.x + threadIdx.x;
    if (e >= NEDGE) return;
    atomicAdd(&g_cnt[__ldg(ei + NEDGE + e)], 1);
}

// per-block exclusive scan of a 1024 chunk; block total -> g_bsum
__global__ __launch_bounds__(1024) void k_scan1() {
    __shared__ int wsum[32];
    int tid = threadIdx.x, lane = tid & 31, wid = tid >> 5;
    int i = blockIdx.x * 1024 + tid;
    int v = (i < NATOMS) ? g_cnt[i] : 0;
    int incl = v;
    #pragma unroll
    for (int off = 1; off < 32; off <<= 1) {
        int n = __shfl_up_sync(0xffffffffu, incl, off);
        if (lane >= off) incl += n;
    }
    if (lane == 31) wsum[wid] = incl;
    __syncthreads();
    if (wid == 0) {
        int wv = wsum[lane];
        int wincl = wv;
        #pragma unroll
        for (int off = 1; off < 32; off <<= 1) {
            int n = __shfl_up_sync(0xffffffffu, wincl, off);
            if (lane >= off) wincl += n;
        }
        wsum[lane] = wincl - wv;
    }
    __syncthreads();
    int excl = wsum[wid] + incl - v;
    if (i < NATOMS) g_rp[i] = excl;
    if (tid == 1023) g_bsum[blockIdx.x] = excl + v;
}

// exclusive scan of NSCANB block sums (one 64-thread block)
__global__ void k_scan2() {
    __shared__ int ws[2];
    int tid = threadIdx.x, lane = tid & 31;
    int v = (tid < NSCANB) ? g_bsum[tid] : 0;
    int incl = v;
    #pragma unroll
    for (int off = 1; off < 32; off <<= 1) {
        int n = __shfl_up_sync(0xffffffffu, incl, off);
        if (lane >= off) incl += n;
    }
    if (lane == 31) ws[tid >> 5] = incl;
    __syncthreads();
    int add = (tid >= 32) ? ws[0] : 0;
    if (tid < NSCANB) g_bsum[tid] = incl - v + add;
}

// add block offsets, init cursors
__global__ __launch_bounds__(1024) void k_scan3() {
    int i = blockIdx.x * 1024 + threadIdx.x;
    if (i < NATOMS) {
        int r = g_rp[i] + g_bsum[blockIdx.x];
        g_rp[i] = r;
        g_cur[i] = r;
    }
    if (i == 0) g_rp[NATOMS] = NEDGE;
}

// distance + table coord; scatter (src, x) to dst-sorted position
__global__ void k_scatter(const float* __restrict__ pos, const int* __restrict__ ei) {
    int e = blockIdx.x * blockDim.x + threadIdx.x;
    if (e >= NEDGE) return;
    int s = __ldg(ei + e);
    int t = __ldg(ei + NEDGE + e);
    float dx = __ldg(pos + 3 * t + 0) - __ldg(pos + 3 * s + 0);
    float dy = __ldg(pos + 3 * t + 1) - __ldg(pos + 3 * s + 1);
    float dz = __ldg(pos + 3 * t + 2) - __ldg(pos + 3 * s + 2);
    float d = sqrtf(dx * dx + dy * dy + dz * dz);
    float x = fminf(d * TABSCALE, (float)(MTAB - 1) - 0.001f);
    int p = atomicAdd(&g_cur[t], 1);
    g_srcx[p] = make_uint2((unsigned)s, __float_as_uint(x));
}

// ---------------- build Wf(d) table (fp16): [NB][MTAB][64] -------------------
__global__ __launch_bounds__(64) void k_table(
    const float* __restrict__ w1, const float* __restrict__ b1,
    const float* __restrict__ w2, const float* __restrict__ b2)
{
    __shared__ float w1s[NGAUSS * 64];
    __shared__ float w2s[64 * 64];
    __shared__ float b1s[64], b2s[64];
    __shared__ float rbfs[NGAUSS];
    __shared__ float t1s[64];

    const int KPB = 32;
    int t  = blockIdx.x / (MTAB / KPB);
    int kb = blockIdx.x % (MTAB / KPB);
    int tid = threadIdx.x;

    for (int i = tid; i < NGAUSS * 64; i += 64) w1s[i] = w1[t * NGAUSS * 64 + i];
    for (int i = tid; i < 64 * 64;     i += 64) w2s[i] = w2[t * 64 * 64 + i];
    b1s[tid] = b1[t * 64 + tid];
    b2s[tid] = b2[t * 64 + tid];

    const float step  = 10.0f / 49.0f;
    const float coeff = -0.5f / (step * step);

    for (int kk = 0; kk < KPB; kk++) {
        int knot = kb * KPB + kk;
        float dv = (float)knot * TABSTEP;
        __syncthreads();
        if (tid < NGAUSS) {
            float dd = dv - (float)tid * step;
            rbfs[tid] = expf(coeff * dd * dd);
        }
        __syncthreads();
        float a = b1s[tid];
        #pragma unroll 10
        for (int j = 0; j < NGAUSS; j++) a += rbfs[j] * w1s[j * 64 + tid];
        t1s[tid] = ssp(a);
        __syncthreads();
        float a2 = b2s[tid];
        #pragma unroll 16
        for (int k = 0; k < 64; k++) a2 += t1s[k] * w2s[k * 64 + tid];
        float C = 0.5f * (cosf(dv * 0.31415926535897931f) + 1.0f);
        g_tabh[((size_t)t * MTAB + knot) * 64 + tid] = __float2half_rn(a2 * C);
    }
}

// ---------------- fused embed + cf1(t=0) -------------------------------------
// h = emb[z]; hx = h @ W. Quad-shuffle GEMM, 4 lanes per row.
__global__ __launch_bounds__(256) void k_embed_cf1(
    const int* __restrict__ z, const float* __restrict__ emb,
    const float* __restrict__ W)
{
    __shared__ float Ws[64 * 64];
    for (int i = threadIdx.x; i < 4096; i += 256) Ws[i] = W[i];
    __syncthreads();

    int row  = blockIdx.x * 64 + (threadIdx.x >> 2);
    int rowc = min(row, NATOMS - 1);
    int q    = threadIdx.x & 3;
    int lane = threadIdx.x & 31;

    int zi = __ldg(z + rowc);
    float xs[16];
    const float4* xr = (const float4*)(emb + (size_t)zi * 64 + q * 16);
    ((float4*)xs)[0] = __ldg(xr);     ((float4*)xs)[1] = __ldg(xr + 1);
    ((float4*)xs)[2] = __ldg(xr + 2); ((float4*)xs)[3] = __ldg(xr + 3);

    float acc[16];
    #pragma unroll
    for (int j = 0; j < 16; j++) acc[j] = 0.0f;
    #pragma unroll
    for (int k = 0; k < 64; k++) {
        float xk = __shfl_sync(0xffffffffu, xs[k & 15], (lane & ~3) | (k >> 4), 32);
        const float* wr = Ws + k * 64 + q * 16;
        #pragma unroll
        for (int j = 0; j < 16; j++) acc[j] = fmaf(xk, wr[j], acc[j]);
    }

    if (row < NATOMS) {
        float4* hp = (float4*)(g_h + (size_t)row * 64 + q * 16);
        hp[0] = ((float4*)xs)[0]; hp[1] = ((float4*)xs)[1];
        hp[2] = ((float4*)xs)[2]; hp[3] = ((float4*)xs)[3];
        __half2 hv[8];
        #pragma unroll
        for (int j = 0; j < 8; j++) hv[j] = __floats2half2_rn(acc[2 * j], acc[2 * j + 1]);
        uint4* dstp = (uint4*)(g_hxh + (size_t)row * 64 + q * 16);
        dstp[0] = *(uint4*)(hv);
        dstp[1] = *(uint4*)(hv + 4);
    }
}

// ---------------- gather-aggregate -------------------------------------------
// one warp/node, 2 features/lane; records staged lane-parallel, shfl broadcast,
// inner loop unrolled x4 for independent load issue.
__global__ __launch_bounds__(256) void k_agg(int t) {
    int node = blockIdx.x * 8 + (threadIdx.x >> 5);
    if (node >= NATOMS) return;
    int lane = threadIdx.x & 31;
    int beg = __ldg(&g_rp[node]), end = __ldg(&g_rp[node + 1]);

    float a0 = 0.0f, a1 = 0.0f;
    const __half* tb = g_tabh + (size_t)t * MTAB * 64;

    for (int base = beg; base < end; base += 32) {
        uint2 rec = make_uint2(0u, 0u);
        if (base + lane < end) rec = __ldg(&g_srcx[base + lane]);
        int n = min(32, end - base);
        int j = 0;
        for (; j + 4 <= n; j += 4) {
            unsigned s0 = __shfl_sync(0xffffffffu, rec.x, j);
            unsigned s1 = __shfl_sync(0xffffffffu, rec.x, j + 1);
            unsigned s2 = __shfl_sync(0xffffffffu, rec.x, j + 2);
            unsigned s3 = __shfl_sync(0xffffffffu, rec.x, j + 3);
            float x0 = __uint_as_float(__shfl_sync(0xffffffffu, rec.y, j));
            float x1 = __uint_as_float(__shfl_sync(0xffffffffu, rec.y, j + 1));
            float x2 = __uint_as_float(__shfl_sync(0xffffffffu, rec.y, j + 2));
            float x3 = __uint_as_float(__shfl_sync(0xffffffffu, rec.y, j + 3));
            int   r0 = (int)x0, r1 = (int)x1, r2 = (int)x2, r3 = (int)x3;
            float w0 = x0 - (float)r0, w1 = x1 - (float)r1;
            float w2 = x2 - (float)r2, w3 = x3 - (float)r3;
            const __half2* t0 = (const __half2*)(tb + (size_t)r0 * 64) + lane;
            const __half2* t1 = (const __half2*)(tb + (size_t)r1 * 64) + lane;
            const __half2* t2 = (const __half2*)(tb + (size_t)r2 * 64) + lane;
            const __half2* t3 = (const __half2*)(tb + (size_t)r3 * 64) + lane;
            float2 a0f = __half22float2(__ldg(t0)), b0f = __half22float2(__ldg(t0 + 32));
            float2 a1f = __half22float2(__ldg(t1)), b1f = __half22float2(__ldg(t1 + 32));
            float2 a2f = __half22float2(__ldg(t2)), b2f = __half22float2(__ldg(t2 + 32));
            float2 a3f = __half22float2(__ldg(t3)), b3f = __half22float2(__ldg(t3 + 32));
            float2 h0 = __half22float2(__ldg((const __half2*)(g_hxh + (size_t)s0 * 64) + lane));
            float2 h1 = __half22float2(__ldg((const __half2*)(g_hxh + (size_t)s1 * 64) + lane));
            float2 h2 = __half22float2(__ldg((const __half2*)(g_hxh + (size_t)s2 * 64) + lane));
            float2 h3 = __half22float2(__ldg((const __half2*)(g_hxh + (size_t)s3 * 64) + lane));
            a0 = fmaf(h0.x, fmaf(w0, b0f.x - a0f.x, a0f.x), a0);
            a1 = fmaf(h0.y, fmaf(w0, b0f.y - a0f.y, a0f.y), a1);
            a0 = fmaf(h1.x, fmaf(w1, b1f.x - a1f.x, a1f.x), a0);
            a1 = fmaf(h1.y, fmaf(w1, b1f.y - a1f.y, a1f.y), a1);
            a0 = fmaf(h2.x, fmaf(w2, b2f.x - a2f.x, a2f.x), a0);
            a1 = fmaf(h2.y, fmaf(w2, b2f.y - a2f.y, a2f.y), a1);
            a0 = fmaf(h3.x, fmaf(w3, b3f.x - a3f.x, a3f.x), a0);
            a1 = fmaf(h3.y, fmaf(w3, b3f.y - a3f.y, a3f.y), a1);
        }
        for (; j < n; j++) {
            unsigned s = __shfl_sync(0xffffffffu, rec.x, j);
            float x = __uint_as_float(__shfl_sync(0xffffffffu, rec.y, j));
            int r0 = (int)x;
            float w = x - (float)r0;
            const __half2* ta = (const __half2*)(tb + (size_t)r0 * 64) + lane;
            float2 af = __half22float2(__ldg(ta));
            float2 bf = __half22float2(__ldg(ta + 32));
            float2 hf = __half22float2(__ldg((const __half2*)(g_hxh + (size_t)s * 64) + lane));
            a0 = fmaf(hf.x, fmaf(w, bf.x - af.x, af.x), a0);
            a1 = fmaf(hf.y, fmaf(w, bf.y - af.y, af.y), a1);
        }
    }
    ((float2*)g_agg)[(size_t)node * 32 + lane] = make_float2(a0, a1);
}

// ---------------- fused: h += ssp(agg@W1+b1)@W2+b2 ; hx = h@W3 ---------------
template <bool FUSE_NEXT>
__global__ __launch_bounds__(256) void k_cf2lin(
    const float* __restrict__ W1, const float* __restrict__ B1,
    const float* __restrict__ W2, const float* __restrict__ B2,
    const float* __restrict__ W3)
{
    __shared__ float W1s[64 * 64];
    __shared__ float W2s[64 * 64];
    __shared__ float W3s[64 * 64];
    for (int i = threadIdx.x; i < 4096; i += 256) {
        W1s[i] = W1[i];
        W2s[i] = W2[i];
        if (FUSE_NEXT) W3s[i] = W3[i];
    }
    __syncthreads();

    int row  = blockIdx.x * 64 + (threadIdx.x >> 2);
    int rowc = min(row, NATOMS - 1);
    int q    = threadIdx.x & 3;
    int lane = threadIdx.x & 31;

    float xs[16];
    const float4* xr = (const float4*)(g_agg + (size_t)rowc * 64 + q * 16);
    ((float4*)xs)[0] = xr[0]; ((float4*)xs)[1] = xr[1];
    ((float4*)xs)[2] = xr[2]; ((float4*)xs)[3] = xr[3];

    float acc[16];
    #pragma unroll
    for (int j = 0; j < 16; j++) acc[j] = B1[q * 16 + j];
    #pragma unroll
    for (int k = 0; k < 64; k++) {
        float xk = __shfl_sync(0xffffffffu, xs[k & 15], (lane & ~3) | (k >> 4), 32);
        const float* wr = W1s + k * 64 + q * 16;
        #pragma unroll
        for (int j = 0; j < 16; j++) acc[j] = fmaf(xk, wr[j], acc[j]);
    }

    float us[16];
    #pragma unroll
    for (int j = 0; j < 16; j++) us[j] = ssp(acc[j]);

    #pragma unroll
    for (int j = 0; j < 16; j++) acc[j] = B2[q * 16 + j];
    #pragma unroll
    for (int k = 0; k < 64; k++) {
        float uk = __shfl_sync(0xffffffffu, us[k & 15], (lane & ~3) | (k >> 4), 32);
        const float* wr = W2s + k * 64 + q * 16;
        #pragma unroll
        for (int j = 0; j < 16; j++) acc[j] = fmaf(uk, wr[j], acc[j]);
    }

    // residual: hnew = h_old + acc
    float hn[16];
    const float4* hr = (const float4*)(g_h + (size_t)rowc * 64 + q * 16);
    float4 h0 = hr[0], h1 = hr[1], h2 = hr[2], h3 = hr[3];
    hn[0] = h0.x + acc[0];  hn[1] = h0.y + acc[1];  hn[2] = h0.z + acc[2];  hn[3] = h0.w + acc[3];
    hn[4] = h1.x + acc[4];  hn[5] = h1.y + acc[5];  hn[6] = h1.z + acc[6];  hn[7] = h1.w + acc[7];
    hn[8] = h2.x + acc[8];  hn[9] = h2.y + acc[9];  hn[10] = h2.z + acc[10]; hn[11] = h2.w + acc[11];
    hn[12] = h3.x + acc[12]; hn[13] = h3.y + acc[13]; hn[14] = h3.z + acc[14]; hn[15] = h3.w + acc[15];

    if (row < NATOMS) {
        float4* hp = (float4*)(g_h + (size_t)row * 64 + q * 16);
        hp[0] = ((float4*)hn)[0]; hp[1] = ((float4*)hn)[1];
        hp[2] = ((float4*)hn)[2]; hp[3] = ((float4*)hn)[3];
    }

    if (FUSE_NEXT) {
        #pragma unroll
        for (int j = 0; j < 16; j++) acc[j] = 0.0f;
        #pragma unroll
        for (int k = 0; k < 64; k++) {
            float hk = __shfl_sync(0xffffffffu, hn[k & 15], (lane & ~3) | (k >> 4), 32);
            const float* wr = W3s + k * 64 + q * 16;
            #pragma unroll
            for (int j = 0; j < 16; j++) acc[j] = fmaf(hk, wr[j], acc[j]);
        }
        if (row < NATOMS) {
            __half2 hv[8];
            #pragma unroll
            for (int j = 0; j < 8; j++) hv[j] = __floats2half2_rn(acc[2 * j], acc[2 * j + 1]);
            uint4* dstp = (uint4*)(g_hxh + (size_t)row * 64 + q * 16);
            dstp[0] = *(uint4*)(hv);
            dstp[1] = *(uint4*)(hv + 4);
        }
    }
}

// ---------------- graph readout scatter --------------------------------------
__global__ void k_scatter_g(const int* __restrict__ batch) {
    int gid = blockIdx.x * blockDim.x + threadIdx.x;
    int i = gid >> 4;
    if (i >= NATOMS) return;
    int lane = (gid & 15) * 4;
    int b = __ldg(batch + i);
    float4 v = *(const float4*)(g_h + (size_t)i * 64 + lane);
    float* addr = g_gr + (size_t)b * 64 + lane;
    asm volatile("red.global.add.v4.f32 [%0], {%1,%2,%3,%4};"
                 :: "l"(addr), "f"(v.x), "f"(v.y), "f"(v.z), "f"(v.w)
                 : "memory");
}

// ---------------- output head --------------------------------------------------
__global__ __launch_bounds__(256) void k_head(
    const float* __restrict__ W1, const float* __restrict__ B1,
    const float* __restrict__ W2, const float* __restrict__ B2,
    float* __restrict__ out)
{
    __shared__ float w1s[64 * 32];
    __shared__ float w2s[32];
    __shared__ float b1s[32];
    for (int i = threadIdx.x; i < 2048; i += 256) w1s[i] = W1[i];
    if (threadIdx.x < 32) { w2s[threadIdx.x] = W2[threadIdx.x]; b1s[threadIdx.x] = B1[threadIdx.x]; }
    __syncthreads();
    int g = threadIdx.x;
    if (g >= NGRAPH) return;
    float gv[64];
    #pragma unroll 16
    for (int k = 0; k < 64; k++) gv[k] = g_gr[g * 64 + k];
    float o = B2[0];
    #pragma unroll 4
    for (int j = 0; j < 32; j++) {
        float a = b1s[j];
        #pragma unroll 16
        for (int k = 0; k < 64; k++) a += gv[k] * w1s[k * 32 + j];
        o += fmaxf(a, 0.0f) * w2s[j];
    }
    out[g] = o;
}

// ---------------- launcher ------------------------------------------------------
extern "C" void kernel_launch(void* const* d_in, const int* in_sizes, int n_in,
                              void* d_out, int out_size) {
    const int*   z      = (const int*)  d_in[0];
    const float* pos    = (const float*)d_in[1];
    const int*   batch  = (const int*)  d_in[2];
    const int*   ei     = (const int*)  d_in[3];
    const float* emb    = (const float*)d_in[4];
    const float* mlp_w1 = (const float*)d_in[5];
    const float* mlp_b1 = (const float*)d_in[6];
    const float* mlp_w2 = (const float*)d_in[7];
    const float* mlp_b2 = (const float*)d_in[8];
    const float* cf1_w  = (const float*)d_in[9];
    const float* cf2_w  = (const float*)d_in[10];
    const float* cf2_b  = (const float*)d_in[11];
    const float* lin_w  = (const float*)d_in[12];
    const float* lin_b  = (const float*)d_in[13];
    const float* out1_w = (const float*)d_in[14];
    const float* out1_b = (const float*)d_in[15];
    const float* out2_w = (const float*)d_in[16];
    const float* out2_b = (const float*)d_in[17];
    float* out = (float*)d_out;

    // CSR build (edge_index constant across interactions)
    k_zero   <<<(NATOMS + 255) / 256, 256>>>();
    k_hist   <<<(NEDGE + 255) / 256, 256>>>(ei);
    k_scan1  <<<NSCANB, 1024>>>();
    k_scan2  <<<1, 64>>>();
    k_scan3  <<<NSCANB, 1024>>>();
    k_scatter<<<(NEDGE + 255) / 256, 256>>>(pos, ei);

    k_table<<<NB * (MTAB / 32), 64>>>(mlp_w1, mlp_b1, mlp_w2, mlp_b2);
    k_embed_cf1<<<(NATOMS + 63) / 64, 256>>>(z, emb, cf1_w);

    for (int t = 0; t < NB; t++) {
        k_agg<<<(NATOMS + 7) / 8, 256>>>(t);
        const float* w1 = cf2_w + (size_t)t * 64 * 64;
        const float* b1 = cf2_b + (size_t)t * 64;
        const float* w2 = lin_w + (size_t)t * 64 * 64;
        const float* b2 = lin_b + (size_t)t * 64;
        if (t + 1 < NB)
            k_cf2lin<true><<<(NATOMS + 63) / 64, 256>>>(w1, b1, w2, b2,
                cf1_w + (size_t)(t + 1) * 64 * 64);
        else
            k_cf2lin<false><<<(NATOMS + 63) / 64, 256>>>(w1, b1, w2, b2, nullptr);
    }

    k_scatter_g<<<(NATOMS * 16 + 255) / 256, 256>>>(batch);
    k_head<<<1, 256>>>(out1_w, out1_b, out2_w, out2_b, out);
}

// round 4
// speedup vs baseline: 1.5534x; 1.0762x over previous
#include <cuda_runtime.h>
#include <cuda_fp16.h>
#include <math.h>

#define NATOMS  50000
#define NEDGE   1600000
#define NGRAPH  250
#define HDIM    64
#define NGAUSS  50
#define NB      3
#define MTAB    8192
#define TABMAX  8.6700f     // > 5*sqrt(3) = 8.66025
#define TABSCALE ((float)(MTAB - 1) / TABMAX)
#define TABSTEP  (TABMAX / (float)(MTAB - 1))
#define NSCANB  49          // ceil(NATOMS / 1024)

// ---------------- scratch (device globals; no allocation allowed) ----------
// paired table: per knot 128 halves = [64 A values][64 D=A(k+1)-A(k) values]
__device__ __half g_tabp[NB * MTAB * 128];      // 6.3 MB
__device__ float  g_h[NATOMS * HDIM];           // 12.8 MB node features
__device__ __half g_hxh[NATOMS * HDIM];         // 6.4 MB  h @ cf1_w, fp16
__device__ float  g_agg[NATOMS * HDIM];         // 12.8 MB gather accumulator
__device__ float  g_gr[NGRAPH * HDIM];          // graph readout
__device__ int    g_cnt[NATOMS];                // histogram
__device__ int    g_rp[NATOMS + 1];             // CSR rowptr
__device__ int    g_cur[NATOMS];                // scatter cursors
__device__ int    g_bsum[64];                   // scan block sums
__device__ uint2  g_srcx[NEDGE];                // dst-sorted (src, x) records

__device__ __forceinline__ float ssp(float v) {
    return fmaxf(v, 0.0f) + log1pf(expf(-fabsf(v))) - 0.6931471805599453f;
}

// ---------------- CSR build --------------------------------------------------
__global__ void k_zero() {
    int i = blockIdx.x * blockDim.x + threadIdx.x;
    if (i < NATOMS) g_cnt[i] = 0;
    if (i < NGRAPH * HDIM) g_gr[i] = 0.0f;
}

__global__ void k_hist(const int* __restrict__ ei) {
    int e = blockIdx.x * blockDim.x + threadIdx.x;
    if (e >= NEDGE) return;
    atomicAdd(&g_cnt[__ldg(ei + NEDGE + e)], 1);
}

__global__ __launch_bounds__(1024) void k_scan1() {
    __shared__ int wsum[32];
    int tid = threadIdx.x, lane = tid & 31, wid = tid >> 5;
    int i = blockIdx.x * 1024 + tid;
    int v = (i < NATOMS) ? g_cnt[i] : 0;
    int incl = v;
    #pragma unroll
    for (int off = 1; off < 32; off <<= 1) {
        int n = __shfl_up_sync(0xffffffffu, incl, off);
        if (lane >= off) incl += n;
    }
    if (lane == 31) wsum[wid] = incl;
    __syncthreads();
    if (wid == 0) {
        int wv = wsum[lane];
        int wincl = wv;
        #pragma unroll
        for (int off = 1; off < 32; off <<= 1) {
            int n = __shfl_up_sync(0xffffffffu, wincl, off);
            if (lane >= off) wincl += n;
        }
        wsum[lane] = wincl - wv;
    }
    __syncthreads();
    int excl = wsum[wid] + incl - v;
    if (i < NATOMS) g_rp[i] = excl;
    if (tid == 1023) g_bsum[blockIdx.x] = excl + v;
}

__global__ void k_scan2() {
    __shared__ int ws[2];
    int tid = threadIdx.x, lane = tid & 31;
    int v = (tid < NSCANB) ? g_bsum[tid] : 0;
    int incl = v;
    #pragma unroll
    for (int off = 1; off < 32; off <<= 1) {
        int n = __shfl_up_sync(0xffffffffu, incl, off);
        if (lane >= off) incl += n;
    }
    if (lane == 31) ws[tid >> 5] = incl;
    __syncthreads();
    int add = (tid >= 32) ? ws[0] : 0;
    if (tid < NSCANB) g_bsum[tid] = incl - v + add;
}

__global__ __launch_bounds__(1024) void k_scan3() {
    int i = blockIdx.x * 1024 + threadIdx.x;
    if (i < NATOMS) {
        int r = g_rp[i] + g_bsum[blockIdx.x];
        g_rp[i] = r;
        g_cur[i] = r;
    }
    if (i == 0) g_rp[NATOMS] = NEDGE;
}

__global__ void k_scatter(const float* __restrict__ pos, const int* __restrict__ ei) {
    int e = blockIdx.x * blockDim.x + threadIdx.x;
    if (e >= NEDGE) return;
    int s = __ldg(ei + e);
    int t = __ldg(ei + NEDGE + e);
    float dx = __ldg(pos + 3 * t + 0) - __ldg(pos + 3 * s + 0);
    float dy = __ldg(pos + 3 * t + 1) - __ldg(pos + 3 * s + 1);
    float dz = __ldg(pos + 3 * t + 2) - __ldg(pos + 3 * s + 2);
    float d = sqrtf(dx * dx + dy * dy + dz * dz);
    float x = fminf(d * TABSCALE, (float)(MTAB - 1) - 0.001f);
    int p = atomicAdd(&g_cur[t], 1);
    g_srcx[p] = make_uint2((unsigned)s, __float_as_uint(x));
}

// ---------------- build Wf(d) table A-part (fp16) ----------------------------
__global__ __launch_bounds__(64) void k_table(
    const float* __restrict__ w1, const float* __restrict__ b1,
    const float* __restrict__ w2, const float* __restrict__ b2)
{
    __shared__ float w1s[NGAUSS * 64];
    __shared__ float w2s[64 * 64];
    __shared__ float b1s[64], b2s[64];
    __shared__ float rbfs[NGAUSS];
    __shared__ float t1s[64];

    const int KPB = 32;
    int t  = blockIdx.x / (MTAB / KPB);
    int kb = blockIdx.x % (MTAB / KPB);
    int tid = threadIdx.x;

    for (int i = tid; i < NGAUSS * 64; i += 64) w1s[i] = w1[t * NGAUSS * 64 + i];
    for (int i = tid; i < 64 * 64;     i += 64) w2s[i] = w2[t * 64 * 64 + i];
    b1s[tid] = b1[t * 64 + tid];
    b2s[tid] = b2[t * 64 + tid];

    const float step  = 10.0f / 49.0f;
    const float coeff = -0.5f / (step * step);

    for (int kk = 0; kk < KPB; kk++) {
        int knot = kb * KPB + kk;
        float dv = (float)knot * TABSTEP;
        __syncthreads();
        if (tid < NGAUSS) {
            float dd = dv - (float)tid * step;
            rbfs[tid] = expf(coeff * dd * dd);
        }
        __syncthreads();
        float a = b1s[tid];
        #pragma unroll 10
        for (int j = 0; j < NGAUSS; j++) a += rbfs[j] * w1s[j * 64 + tid];
        t1s[tid] = ssp(a);
        __syncthreads();
        float a2 = b2s[tid];
        #pragma unroll 16
        for (int k = 0; k < 64; k++) a2 += t1s[k] * w2s[k * 64 + tid];
        float C = 0.5f * (cosf(dv * 0.31415926535897931f) + 1.0f);
        g_tabp[((size_t)t * MTAB + knot) * 128 + tid] = __float2half_rn(a2 * C);
    }
}

// ---------------- table D-part: D[k] = A[k+1] - A[k] -------------------------
__global__ void k_tabdelta() {
    int i = blockIdx.x * 256 + threadIdx.x;
    if (i >= NB * MTAB * 64) return;
    int f  = i & 63;
    int kn = (i >> 6) % MTAB;
    int t  = i / (MTAB * 64);
    size_t rowb = ((size_t)t * MTAB + kn) * 128;
    __half a0 = g_tabp[rowb + f];
    __half a1 = (kn + 1 < MTAB) ? g_tabp[rowb + 128 + f] : a0;
    g_tabp[rowb + 64 + f] = __hsub(a1, a0);
}

// ---------------- fused embed + cf1(t=0) -------------------------------------
__global__ __launch_bounds__(256) void k_embed_cf1(
    const int* __restrict__ z, const float* __restrict__ emb,
    const float* __restrict__ W)
{
    __shared__ float Ws[64 * 64];
    for (int i = threadIdx.x; i < 4096; i += 256) Ws[i] = W[i];
    __syncthreads();

    int row  = blockIdx.x * 64 + (threadIdx.x >> 2);
    int rowc = min(row, NATOMS - 1);
    int q    = threadIdx.x & 3;
    int lane = threadIdx.x & 31;

    int zi = __ldg(z + rowc);
    float xs[16];
    const float4* xr = (const float4*)(emb + (size_t)zi * 64 + q * 16);
    ((float4*)xs)[0] = __ldg(xr);     ((float4*)xs)[1] = __ldg(xr + 1);
    ((float4*)xs)[2] = __ldg(xr + 2); ((float4*)xs)[3] = __ldg(xr + 3);

    float acc[16];
    #pragma unroll
    for (int j = 0; j < 16; j++) acc[j] = 0.0f;
    #pragma unroll
    for (int k = 0; k < 64; k++) {
        float xk = __shfl_sync(0xffffffffu, xs[k & 15], (lane & ~3) | (k >> 4), 32);
        const float* wr = Ws + k * 64 + q * 16;
        #pragma unroll
        for (int j = 0; j < 16; j++) acc[j] = fmaf(xk, wr[j], acc[j]);
    }

    if (row < NATOMS) {
        float4* hp = (float4*)(g_h + (size_t)row * 64 + q * 16);
        hp[0] = ((float4*)xs)[0]; hp[1] = ((float4*)xs)[1];
        hp[2] = ((float4*)xs)[2]; hp[3] = ((float4*)xs)[3];
        __half2 hv[8];
        #pragma unroll
        for (int j = 0; j < 8; j++) hv[j] = __floats2half2_rn(acc[2 * j], acc[2 * j + 1]);
        uint4* dstp = (uint4*)(g_hxh + (size_t)row * 64 + q * 16);
        dstp[0] = *(uint4*)(hv);
        dstp[1] = *(uint4*)(hv + 4);
    }
}

// ---------------- gather-aggregate v3 ----------------------------------------
// one warp/node; 2 edges per warp-instruction (16 lanes each, 4 features/lane);
// table gives (A,D) so lerp = 1 HFMA2; fp32 accumulation; x2 pair unroll.
__device__ __forceinline__ void agg_pair(
    const __half* __restrict__ tb, unsigned s, float x, int fl,
    float& a0, float& a1, float& a2, float& a3)
{
    int   r0 = (int)x;
    __half2 w2 = __float2half2_rn(x - (float)r0);
    const uint2* pt = (const uint2*)(tb + (size_t)r0 * 128) + fl;
    uint2 av = __ldg(pt);
    uint2 dv = __ldg(pt + 16);
    uint2 hv = __ldg((const uint2*)(g_hxh + (size_t)s * 64) + fl);
    __half2 v0 = __hmul2(*(__half2*)&hv.x, __hfma2(w2, *(__half2*)&dv.x, *(__half2*)&av.x));
    __half2 v1 = __hmul2(*(__half2*)&hv.y, __hfma2(w2, *(__half2*)&dv.y, *(__half2*)&av.y));
    float2 f0 = __half22float2(v0);
    float2 f1 = __half22float2(v1);
    a0 += f0.x; a1 += f0.y; a2 += f1.x; a3 += f1.y;
}

__global__ __launch_bounds__(256) void k_agg(int t) {
    int node = blockIdx.x * 8 + (threadIdx.x >> 5);
    if (node >= NATOMS) return;
    int lane = threadIdx.x & 31;
    int half = lane >> 4;
    int fl   = lane & 15;
    int beg = __ldg(&g_rp[node]), end = __ldg(&g_rp[node + 1]);

    float a0 = 0.f, a1 = 0.f, a2 = 0.f, a3 = 0.f;
    const __half* tb = g_tabp + (size_t)t * MTAB * 128;

    for (int base = beg; base < end; base += 32) {
        uint2 rec = make_uint2(0u, 0u);
        if (base + lane < end) rec = __ldg(&g_srcx[base + lane]);
        int n = min(32, end - base);
        int j = 0;
        for (; j + 4 <= n; j += 4) {
            int iA = j + half, iB = j + 2 + half;
            unsigned sA = __shfl_sync(0xffffffffu, rec.x, iA);
            float    xA = __uint_as_float(__shfl_sync(0xffffffffu, rec.y, iA));
            unsigned sB = __shfl_sync(0xffffffffu, rec.x, iB);
            float    xB = __uint_as_float(__shfl_sync(0xffffffffu, rec.y, iB));
            // issue both loads groups before math (independent)
            int r0A = (int)xA, r0B = (int)xB;
            __half2 wA = __float2half2_rn(xA - (float)r0A);
            __half2 wB = __float2half2_rn(xB - (float)r0B);
            const uint2* pA = (const uint2*)(tb + (size_t)r0A * 128) + fl;
            const uint2* pB = (const uint2*)(tb + (size_t)r0B * 128) + fl;
            uint2 avA = __ldg(pA), dvA = __ldg(pA + 16);
            uint2 avB = __ldg(pB), dvB = __ldg(pB + 16);
            uint2 hvA = __ldg((const uint2*)(g_hxh + (size_t)sA * 64) + fl);
            uint2 hvB = __ldg((const uint2*)(g_hxh + (size_t)sB * 64) + fl);
            __half2 vA0 = __hmul2(*(__half2*)&hvA.x, __hfma2(wA, *(__half2*)&dvA.x, *(__half2*)&avA.x));
            __half2 vA1 = __hmul2(*(__half2*)&hvA.y, __hfma2(wA, *(__half2*)&dvA.y, *(__half2*)&avA.y));
            __half2 vB0 = __hmul2(*(__half2*)&hvB.x, __hfma2(wB, *(__half2*)&dvB.x, *(__half2*)&avB.x));
            __half2 vB1 = __hmul2(*(__half2*)&hvB.y, __hfma2(wB, *(__half2*)&dvB.y, *(__half2*)&avB.y));
            float2 fA0 = __half22float2(vA0), fA1 = __half22float2(vA1);
            float2 fB0 = __half22float2(vB0), fB1 = __half22float2(vB1);
            a0 += fA0.x + fB0.x;
            a1 += fA0.y + fB0.y;
            a2 += fA1.x + fB1.x;
            a3 += fA1.y + fB1.y;
        }
        for (; j + 2 <= n; j += 2) {
            int iA = j + half;
            unsigned sA = __shfl_sync(0xffffffffu, rec.x, iA);
            float    xA = __uint_as_float(__shfl_sync(0xffffffffu, rec.y, iA));
            agg_pair(tb, sA, xA, fl, a0, a1, a2, a3);
        }
        if (j < n) {
            unsigned sA = __shfl_sync(0xffffffffu, rec.x, j);
            float    xA = __uint_as_float(__shfl_sync(0xffffffffu, rec.y, j));
            if (half == 0) agg_pair(tb, sA, xA, fl, a0, a1, a2, a3);
        }
    }

    // fold the two edge-halves
    a0 += __shfl_down_sync(0xffffffffu, a0, 16);
    a1 += __shfl_down_sync(0xffffffffu, a1, 16);
    a2 += __shfl_down_sync(0xffffffffu, a2, 16);
    a3 += __shfl_down_sync(0xffffffffu, a3, 16);
    if (half == 0) {
        float4 v = make_float4(a0, a1, a2, a3);
        *(float4*)(g_agg + (size_t)node * 64 + fl * 4) = v;
    }
}

// ---------------- fused: h += ssp(agg@W1+b1)@W2+b2 ; hx = h@W3 ---------------
template <bool FUSE_NEXT>
__global__ __launch_bounds__(256) void k_cf2lin(
    const float* __restrict__ W1, const float* __restrict__ B1,
    const float* __restrict__ W2, const float* __restrict__ B2,
    const float* __restrict__ W3)
{
    __shared__ float W1s[64 * 64];
    __shared__ float W2s[64 * 64];
    __shared__ float W3s[64 * 64];
    for (int i = threadIdx.x; i < 4096; i += 256) {
        W1s[i] = W1[i];
        W2s[i] = W2[i];
        if (FUSE_NEXT) W3s[i] = W3[i];
    }
    __syncthreads();

    int row  = blockIdx.x * 64 + (threadIdx.x >> 2);
    int rowc = min(row, NATOMS - 1);
    int q    = threadIdx.x & 3;
    int lane = threadIdx.x & 31;

    float xs[16];
    const float4* xr = (const float4*)(g_agg + (size_t)rowc * 64 + q * 16);
    ((float4*)xs)[0] = xr[0]; ((float4*)xs)[1] = xr[1];
    ((float4*)xs)[2] = xr[2]; ((float4*)xs)[3] = xr[3];

    float acc[16];
    #pragma unroll
    for (int j = 0; j < 16; j++) acc[j] = B1[q * 16 + j];
    #pragma unroll
    for (int k = 0; k < 64; k++) {
        float xk = __shfl_sync(0xffffffffu, xs[k & 15], (lane & ~3) | (k >> 4), 32);
        const float* wr = W1s + k * 64 + q * 16;
        #pragma unroll
        for (int j = 0; j < 16; j++) acc[j] = fmaf(xk, wr[j], acc[j]);
    }

    float us[16];
    #pragma unroll
    for (int j = 0; j < 16; j++) us[j] = ssp(acc[j]);

    #pragma unroll
    for (int j = 0; j < 16; j++) acc[j] = B2[q * 16 + j];
    #pragma unroll
    for (int k = 0; k < 64; k++) {
        float uk = __shfl_sync(0xffffffffu, us[k & 15], (lane & ~3) | (k >> 4), 32);
        const float* wr = W2s + k * 64 + q * 16;
        #pragma unroll
        for (int j = 0; j < 16; j++) acc[j] = fmaf(uk, wr[j], acc[j]);
    }

    float hn[16];
    const float4* hr = (const float4*)(g_h + (size_t)rowc * 64 + q * 16);
    float4 h0 = hr[0], h1 = hr[1], h2 = hr[2], h3 = hr[3];
    hn[0] = h0.x + acc[0];  hn[1] = h0.y + acc[1];  hn[2] = h0.z + acc[2];  hn[3] = h0.w + acc[3];
    hn[4] = h1.x + acc[4];  hn[5] = h1.y + acc[5];  hn[6] = h1.z + acc[6];  hn[7] = h1.w + acc[7];
    hn[8] = h2.x + acc[8];  hn[9] = h2.y + acc[9];  hn[10] = h2.z + acc[10]; hn[11] = h2.w + acc[11];
    hn[12] = h3.x + acc[12]; hn[13] = h3.y + acc[13]; hn[14] = h3.z + acc[14]; hn[15] = h3.w + acc[15];

    if (row < NATOMS) {
        float4* hp = (float4*)(g_h + (size_t)row * 64 + q * 16);
        hp[0] = ((float4*)hn)[0]; hp[1] = ((float4*)hn)[1];
        hp[2] = ((float4*)hn)[2]; hp[3] = ((float4*)hn)[3];
    }

    if (FUSE_NEXT) {
        #pragma unroll
        for (int j = 0; j < 16; j++) acc[j] = 0.0f;
        #pragma unroll
        for (int k = 0; k < 64; k++) {
            float hk = __shfl_sync(0xffffffffu, hn[k & 15], (lane & ~3) | (k >> 4), 32);
            const float* wr = W3s + k * 64 + q * 16;
            #pragma unroll
            for (int j = 0; j < 16; j++) acc[j] = fmaf(hk, wr[j], acc[j]);
        }
        if (row < NATOMS) {
            __half2 hv[8];
            #pragma unroll
            for (int j = 0; j < 8; j++) hv[j] = __floats2half2_rn(acc[2 * j], acc[2 * j + 1]);
            uint4* dstp = (uint4*)(g_hxh + (size_t)row * 64 + q * 16);
            dstp[0] = *(uint4*)(hv);
            dstp[1] = *(uint4*)(hv + 4);
        }
    }
}

// ---------------- graph readout scatter --------------------------------------
__global__ void k_scatter_g(const int* __restrict__ batch) {
    int gid = blockIdx.x * blockDim.x + threadIdx.x;
    int i = gid >> 4;
    if (i >= NATOMS) return;
    int lane = (gid & 15) * 4;
    int b = __ldg(batch + i);
    float4 v = *(const float4*)(g_h + (size_t)i * 64 + lane);
    float* addr = g_gr + (size_t)b * 64 + lane;
    asm volatile("red.global.add.v4.f32 [%0], {%1,%2,%3,%4};"
                 :: "l"(addr), "f"(v.x), "f"(v.y), "f"(v.z), "f"(v.w)
                 : "memory");
}

// ---------------- output head --------------------------------------------------
__global__ __launch_bounds__(256) void k_head(
    const float* __restrict__ W1, const float* __restrict__ B1,
    const float* __restrict__ W2, const float* __restrict__ B2,
    float* __restrict__ out)
{
    __shared__ float w1s[64 * 32];
    __shared__ float w2s[32];
    __shared__ float b1s[32];
    for (int i = threadIdx.x; i < 2048; i += 256) w1s[i] = W1[i];
    if (threadIdx.x < 32) { w2s[threadIdx.x] = W2[threadIdx.x]; b1s[threadIdx.x] = B1[threadIdx.x]; }
    __syncthreads();
    int g = threadIdx.x;
    if (g >= NGRAPH) return;
    float gv[64];
    #pragma unroll 16
    for (int k = 0; k < 64; k++) gv[k] = g_gr[g * 64 + k];
    float o = B2[0];
    #pragma unroll 4
    for (int j = 0; j < 32; j++) {
        float a = b1s[j];
        #pragma unroll 16
        for (int k = 0; k < 64; k++) a += gv[k] * w1s[k * 32 + j];
        o += fmaxf(a, 0.0f) * w2s[j];
    }
    out[g] = o;
}

// ---------------- launcher ------------------------------------------------------
extern "C" void kernel_launch(void* const* d_in, const int* in_sizes, int n_in,
                              void* d_out, int out_size) {
    const int*   z      = (const int*)  d_in[0];
    const float* pos    = (const float*)d_in[1];
    const int*   batch  = (const int*)  d_in[2];
    const int*   ei     = (const int*)  d_in[3];
    const float* emb    = (const float*)d_in[4];
    const float* mlp_w1 = (const float*)d_in[5];
    const float* mlp_b1 = (const float*)d_in[6];
    const float* mlp_w2 = (const float*)d_in[7];
    const float* mlp_b2 = (const float*)d_in[8];
    const float* cf1_w  = (const float*)d_in[9];
    const float* cf2_w  = (const float*)d_in[10];
    const float* cf2_b  = (const float*)d_in[11];
    const float* lin_w  = (const float*)d_in[12];
    const float* lin_b  = (const float*)d_in[13];
    const float* out1_w = (const float*)d_in[14];
    const float* out1_b = (const float*)d_in[15];
    const float* out2_w = (const float*)d_in[16];
    const float* out2_b = (const float*)d_in[17];
    float* out = (float*)d_out;

    // CSR build (edge_index constant across interactions)
    k_zero   <<<(NATOMS + 255) / 256, 256>>>();
    k_hist   <<<(NEDGE + 255) / 256, 256>>>(ei);
    k_scan1  <<<NSCANB, 1024>>>();
    k_scan2  <<<1, 64>>>();
    k_scan3  <<<NSCANB, 1024>>>();
    k_scatter<<<(NEDGE + 255) / 256, 256>>>(pos, ei);

    k_table   <<<NB * (MTAB / 32), 64>>>(mlp_w1, mlp_b1, mlp_w2, mlp_b2);
    k_tabdelta<<<(NB * MTAB * 64 + 255) / 256, 256>>>();
    k_embed_cf1<<<(NATOMS + 63) / 64, 256>>>(z, emb, cf1_w);

    for (int t = 0; t < NB; t++) {
        k_agg<<<(NATOMS + 7) / 8, 256>>>(t);
        const float* w1 = cf2_w + (size_t)t * 64 * 64;
        const float* b1 = cf2_b + (size_t)t * 64;
        const float* w2 = lin_w + (size_t)t * 64 * 64;
        const float* b2 = lin_b + (size_t)t * 64;
        if (t + 1 < NB)
            k_cf2lin<true><<<(NATOMS + 63) / 64, 256>>>(w1, b1, w2, b2,
                cf1_w + (size_t)(t + 1) * 64 * 64);
        else
            k_cf2lin<false><<<(NATOMS + 63) / 64, 256>>>(w1, b1, w2, b2, nullptr);
    }

    k_scatter_g<<<(NATOMS * 16 + 255) / 256, 256>>>(batch);
    k_head<<<1, 256>>>(out1_w, out1_b, out2_w, out2_b, out);
}

// round 5
// speedup vs baseline: 1.6012x; 1.0307x over previous
#include <cuda_runtime.h>
#include <cuda_fp16.h>
#include <math.h>

#define NATOMS  50000
#define NEDGE   1600000
#define NGRAPH  250
#define HDIM    64
#define NGAUSS  50
#define NB      3
#define MTAB    8192
#define KBITS   13          // knot bits; src uses upper 17 bits (50000 < 2^17)
#define TABMAX  8.6700f     // > 5*sqrt(3) = 8.66025
#define TABSCALE ((float)(MTAB - 1) / TABMAX)
#define TABSTEP  (TABMAX / (float)(MTAB - 1))
#define NSCANB  49          // ceil(NATOMS / 1024)

// ---------------- scratch (device globals; no allocation allowed) ----------
__device__ __half    g_tabh[NB * MTAB * HDIM];  // 3.1 MB  Wf(d) table, fp16
__device__ float     g_h[NATOMS * HDIM];        // 12.8 MB node features
__device__ __half    g_hxh[NATOMS * HDIM];      // 6.4 MB  h @ cf1_w, fp16
__device__ float     g_agg[NATOMS * HDIM];      // 12.8 MB gather accumulator
__device__ float     g_gr[NGRAPH * HDIM];       // graph readout
__device__ int       g_cnt[NATOMS];             // histogram
__device__ int       g_rp[NATOMS + 1];          // CSR rowptr
__device__ int       g_cur[NATOMS];             // scatter cursors
__device__ int       g_bsum[64];                // scan block sums
__device__ unsigned  g_src[NEDGE];              // dst-sorted packed (src<<13 | knot)

__device__ __forceinline__ float ssp(float v) {
    return fmaxf(v, 0.0f) + log1pf(expf(-fabsf(v))) - 0.6931471805599453f;
}

// ---------------- CSR build --------------------------------------------------
__global__ void k_zero() {
    int i = blockIdx.x * blockDim.x + threadIdx.x;
    if (i < NATOMS) g_cnt[i] = 0;
    if (i < NGRAPH * HDIM) g_gr[i] = 0.0f;
}

__global__ void k_hist(const int* __restrict__ ei) {
    int e = blockIdx.x * blockDim.x + threadIdx.x;
    if (e >= NEDGE) return;
    atomicAdd(&g_cnt[__ldg(ei + NEDGE + e)], 1);
}

__global__ __launch_bounds__(1024) void k_scan1() {
    __shared__ int wsum[32];
    int tid = threadIdx.x, lane = tid & 31, wid = tid >> 5;
    int i = blockIdx.x * 1024 + tid;
    int v = (i < NATOMS) ? g_cnt[i] : 0;
    int incl = v;
    #pragma unroll
    for (int off = 1; off < 32; off <<= 1) {
        int n = __shfl_up_sync(0xffffffffu, incl, off);
        if (lane >= off) incl += n;
    }
    if (lane == 31) wsum[wid] = incl;
    __syncthreads();
    if (wid == 0) {
        int wv = wsum[lane];
        int wincl = wv;
        #pragma unroll
        for (int off = 1; off < 32; off <<= 1) {
            int n = __shfl_up_sync(0xffffffffu, wincl, off);
            if (lane >= off) wincl += n;
        }
        wsum[lane] = wincl - wv;
    }
    __syncthreads();
    int excl = wsum[wid] + incl - v;
    if (i < NATOMS) g_rp[i] = excl;
    if (tid == 1023) g_bsum[blockIdx.x] = excl + v;
}

__global__ void k_scan2() {
    __shared__ int ws[2];
    int tid = threadIdx.x, lane = tid & 31;
    int v = (tid < NSCANB) ? g_bsum[tid] : 0;
    int incl = v;
    #pragma unroll
    for (int off = 1; off < 32; off <<= 1) {
        int n = __shfl_up_sync(0xffffffffu, incl, off);
        if (lane >= off) incl += n;
    }
    if (lane == 31) ws[tid >> 5] = incl;
    __syncthreads();
    int add = (tid >= 32) ? ws[0] : 0;
    if (tid < NSCANB) g_bsum[tid] = incl - v + add;
}

__global__ __launch_bounds__(1024) void k_scan3() {
    int i = blockIdx.x * 1024 + threadIdx.x;
    if (i < NATOMS) {
        int r = g_rp[i] + g_bsum[blockIdx.x];
        g_rp[i] = r;
        g_cur[i] = r;
    }
    if (i == 0) g_rp[NATOMS] = NEDGE;
}

// distance -> nearest knot; scatter packed (src<<13 | knot) to dst-sorted slot
__global__ void k_scatter(const float* __restrict__ pos, const int* __restrict__ ei) {
    int e = blockIdx.x * blockDim.x + threadIdx.x;
    if (e >= NEDGE) return;
    int s = __ldg(ei + e);
    int t = __ldg(ei + NEDGE + e);
    float dx = __ldg(pos + 3 * t + 0) - __ldg(pos + 3 * s + 0);
    float dy = __ldg(pos + 3 * t + 1) - __ldg(pos + 3 * s + 1);
    float dz = __ldg(pos + 3 * t + 2) - __ldg(pos + 3 * s + 2);
    float d = sqrtf(dx * dx + dy * dy + dz * dz);
    int knot = (int)(d * TABSCALE + 0.5f);
    knot = min(knot, MTAB - 1);
    int p = atomicAdd(&g_cur[t], 1);
    g_src[p] = ((unsigned)s << KBITS) | (unsigned)knot;
}

// ---------------- build Wf(d) table (fp16): [NB][MTAB][64] -------------------
__global__ __launch_bounds__(64) void k_table(
    const float* __restrict__ w1, const float* __restrict__ b1,
    const float* __restrict__ w2, const float* __restrict__ b2)
{
    __shared__ float w1s[NGAUSS * 64];
    __shared__ float w2s[64 * 64];
    __shared__ float b1s[64], b2s[64];
    __shared__ float rbfs[NGAUSS];
    __shared__ float t1s[64];

    const int KPB = 32;
    int t  = blockIdx.x / (MTAB / KPB);
    int kb = blockIdx.x % (MTAB / KPB);
    int tid = threadIdx.x;

    for (int i = tid; i < NGAUSS * 64; i += 64) w1s[i] = w1[t * NGAUSS * 64 + i];
    for (int i = tid; i < 64 * 64;     i += 64) w2s[i] = w2[t * 64 * 64 + i];
    b1s[tid] = b1[t * 64 + tid];
    b2s[tid] = b2[t * 64 + tid];

    const float step  = 10.0f / 49.0f;
    const float coeff = -0.5f / (step * step);

    for (int kk = 0; kk < KPB; kk++) {
        int knot = kb * KPB + kk;
        float dv = (float)knot * TABSTEP;
        __syncthreads();
        if (tid < NGAUSS) {
            float dd = dv - (float)tid * step;
            rbfs[tid] = expf(coeff * dd * dd);
        }
        __syncthreads();
        float a = b1s[tid];
        #pragma unroll 10
        for (int j = 0; j < NGAUSS; j++) a += rbfs[j] * w1s[j * 64 + tid];
        t1s[tid] = ssp(a);
        __syncthreads();
        float a2 = b2s[tid];
        #pragma unroll 16
        for (int k = 0; k < 64; k++) a2 += t1s[k] * w2s[k * 64 + tid];
        float C = 0.5f * (cosf(dv * 0.31415926535897931f) + 1.0f);
        g_tabh[((size_t)t * MTAB + knot) * 64 + tid] = __float2half_rn(a2 * C);
    }
}

// ---------------- fused embed + cf1(t=0) -------------------------------------
__global__ __launch_bounds__(256) void k_embed_cf1(
    const int* __restrict__ z, const float* __restrict__ emb,
    const float* __restrict__ W)
{
    __shared__ float Ws[64 * 64];
    for (int i = threadIdx.x; i < 4096; i += 256) Ws[i] = W[i];
    __syncthreads();

    int row  = blockIdx.x * 64 + (threadIdx.x >> 2);
    int rowc = min(row, NATOMS - 1);
    int q    = threadIdx.x & 3;
    int lane = threadIdx.x & 31;

    int zi = __ldg(z + rowc);
    float xs[16];
    const float4* xr = (const float4*)(emb + (size_t)zi * 64 + q * 16);
    ((float4*)xs)[0] = __ldg(xr);     ((float4*)xs)[1] = __ldg(xr + 1);
    ((float4*)xs)[2] = __ldg(xr + 2); ((float4*)xs)[3] = __ldg(xr + 3);

    float acc[16];
    #pragma unroll
    for (int j = 0; j < 16; j++) acc[j] = 0.0f;
    #pragma unroll
    for (int k = 0; k < 64; k++) {
        float xk = __shfl_sync(0xffffffffu, xs[k & 15], (lane & ~3) | (k >> 4), 32);
        const float* wr = Ws + k * 64 + q * 16;
        #pragma unroll
        for (int j = 0; j < 16; j++) acc[j] = fmaf(xk, wr[j], acc[j]);
    }

    if (row < NATOMS) {
        float4* hp = (float4*)(g_h + (size_t)row * 64 + q * 16);
        hp[0] = ((float4*)xs)[0]; hp[1] = ((float4*)xs)[1];
        hp[2] = ((float4*)xs)[2]; hp[3] = ((float4*)xs)[3];
        __half2 hv[8];
        #pragma unroll
        for (int j = 0; j < 8; j++) hv[j] = __floats2half2_rn(acc[2 * j], acc[2 * j + 1]);
        uint4* dstp = (uint4*)(g_hxh + (size_t)row * 64 + q * 16);
        dstp[0] = *(uint4*)(hv);
        dstp[1] = *(uint4*)(hv + 4);
    }
}

// ---------------- gather-aggregate v4 ----------------------------------------
// one warp/node; 4 edges per warp-instruction: 4 groups of 8 lanes, LDG.128
// per lane = 8 fp16 features; nearest-knot table value (no lerp); fp32 accum.
__global__ __launch_bounds__(256) void k_agg(int t) {
    int node = blockIdx.x * 8 + (threadIdx.x >> 5);
    if (node >= NATOMS) return;
    int lane = threadIdx.x & 31;
    int grp  = lane >> 3;       // which edge of the 4-pack
    int fl   = lane & 7;        // 16-byte slot within the 128B feature row
    int beg = __ldg(&g_rp[node]), end = __ldg(&g_rp[node + 1]);

    float a[8];
    #pragma unroll
    for (int i = 0; i < 8; i++) a[i] = 0.0f;
    const __half* tb = g_tabh + (size_t)t * MTAB * 64;

    for (int base = beg; base < end; base += 32) {
        unsigned rec = 0u;
        if (base + lane < end) rec = __ldg(&g_src[base + lane]);
        int n = min(32, end - base);
        #pragma unroll 2
        for (int j = 0; j < n; j += 4) {
            unsigned r = __shfl_sync(0xffffffffu, rec, j + grp);
            if (j + grp < n) {
                unsigned knot = r & (MTAB - 1);
                unsigned src  = r >> KBITS;
                uint4 tv = __ldg((const uint4*)(tb + (size_t)knot * 64) + fl);
                uint4 hv = __ldg((const uint4*)(g_hxh + (size_t)src * 64) + fl);
                __half2 p0 = __hmul2(*(__half2*)&tv.x, *(__half2*)&hv.x);
                __half2 p1 = __hmul2(*(__half2*)&tv.y, *(__half2*)&hv.y);
                __half2 p2 = __hmul2(*(__half2*)&tv.z, *(__half2*)&hv.z);
                __half2 p3 = __hmul2(*(__half2*)&tv.w, *(__half2*)&hv.w);
                float2 f0 = __half22float2(p0);
                float2 f1 = __half22float2(p1);
                float2 f2 = __half22float2(p2);
                float2 f3 = __half22float2(p3);
                a[0] += f0.x; a[1] += f0.y;
                a[2] += f1.x; a[3] += f1.y;
                a[4] += f2.x; a[5] += f2.y;
                a[6] += f3.x; a[7] += f3.y;
            }
        }
    }

    // fold the 4 edge-groups (grp 0..3 -> grp 0)
    #pragma unroll
    for (int i = 0; i < 8; i++) {
        a[i] += __shfl_down_sync(0xffffffffu, a[i], 16);
        a[i] += __shfl_down_sync(0xffffffffu, a[i], 8);
    }
    if (grp == 0) {
        float4* dst = (float4*)(g_agg + (size_t)node * 64 + fl * 8);
        dst[0] = make_float4(a[0], a[1], a[2], a[3]);
        dst[1] = make_float4(a[4], a[5], a[6], a[7]);
    }
}

// ---------------- fused: h += ssp(agg@W1+b1)@W2+b2 ; hx = h@W3 ---------------
template <bool FUSE_NEXT>
__global__ __launch_bounds__(256) void k_cf2lin(
    const float* __restrict__ W1, const float* __restrict__ B1,
    const float* __restrict__ W2, const float* __restrict__ B2,
    const float* __restrict__ W3)
{
    __shared__ float W1s[64 * 64];
    __shared__ float W2s[64 * 64];
    __shared__ float W3s[64 * 64];
    for (int i = threadIdx.x; i < 4096; i += 256) {
        W1s[i] = W1[i];
        W2s[i] = W2[i];
        if (FUSE_NEXT) W3s[i] = W3[i];
    }
    __syncthreads();

    int row  = blockIdx.x * 64 + (threadIdx.x >> 2);
    int rowc = min(row, NATOMS - 1);
    int q    = threadIdx.x & 3;
    int lane = threadIdx.x & 31;

    float xs[16];
    const float4* xr = (const float4*)(g_agg + (size_t)rowc * 64 + q * 16);
    ((float4*)xs)[0] = xr[0]; ((float4*)xs)[1] = xr[1];
    ((float4*)xs)[2] = xr[2]; ((float4*)xs)[3] = xr[3];

    float acc[16];
    #pragma unroll
    for (int j = 0; j < 16; j++) acc[j] = B1[q * 16 + j];
    #pragma unroll
    for (int k = 0; k < 64; k++) {
        float xk = __shfl_sync(0xffffffffu, xs[k & 15], (lane & ~3) | (k >> 4), 32);
        const float* wr = W1s + k * 64 + q * 16;
        #pragma unroll
        for (int j = 0; j < 16; j++) acc[j] = fmaf(xk, wr[j], acc[j]);
    }

    float us[16];
    #pragma unroll
    for (int j = 0; j < 16; j++) us[j] = ssp(acc[j]);

    #pragma unroll
    for (int j = 0; j < 16; j++) acc[j] = B2[q * 16 + j];
    #pragma unroll
    for (int k = 0; k < 64; k++) {
        float uk = __shfl_sync(0xffffffffu, us[k & 15], (lane & ~3) | (k >> 4), 32);
        const float* wr = W2s + k * 64 + q * 16;
        #pragma unroll
        for (int j = 0; j < 16; j++) acc[j] = fmaf(uk, wr[j], acc[j]);
    }

    float hn[16];
    const float4* hr = (const float4*)(g_h + (size_t)rowc * 64 + q * 16);
    float4 h0 = hr[0], h1 = hr[1], h2 = hr[2], h3 = hr[3];
    hn[0] = h0.x + acc[0];  hn[1] = h0.y + acc[1];  hn[2] = h0.z + acc[2];  hn[3] = h0.w + acc[3];
    hn[4] = h1.x + acc[4];  hn[5] = h1.y + acc[5];  hn[6] = h1.z + acc[6];  hn[7] = h1.w + acc[7];
    hn[8] = h2.x + acc[8];  hn[9] = h2.y + acc[9];  hn[10] = h2.z + acc[10]; hn[11] = h2.w + acc[11];
    hn[12] = h3.x + acc[12]; hn[13] = h3.y + acc[13]; hn[14] = h3.z + acc[14]; hn[15] = h3.w + acc[15];

    if (row < NATOMS) {
        float4* hp = (float4*)(g_h + (size_t)row * 64 + q * 16);
        hp[0] = ((float4*)hn)[0]; hp[1] = ((float4*)hn)[1];
        hp[2] = ((float4*)hn)[2]; hp[3] = ((float4*)hn)[3];
    }

    if (FUSE_NEXT) {
        #pragma unroll
        for (int j = 0; j < 16; j++) acc[j] = 0.0f;
        #pragma unroll
        for (int k = 0; k < 64; k++) {
            float hk = __shfl_sync(0xffffffffu, hn[k & 15], (lane & ~3) | (k >> 4), 32);
            const float* wr = W3s + k * 64 + q * 16;
            #pragma unroll
            for (int j = 0; j < 16; j++) acc[j] = fmaf(hk, wr[j], acc[j]);
        }
        if (row < NATOMS) {
            __half2 hv[8];
            #pragma unroll
            for (int j = 0; j < 8; j++) hv[j] = __floats2half2_rn(acc[2 * j], acc[2 * j + 1]);
            uint4* dstp = (uint4*)(g_hxh + (size_t)row * 64 + q * 16);
            dstp[0] = *(uint4*)(hv);
            dstp[1] = *(uint4*)(hv + 4);
        }
    }
}

// ---------------- graph readout scatter --------------------------------------
__global__ void k_scatter_g(const int* __restrict__ batch) {
    int gid = blockIdx.x * blockDim.x + threadIdx.x;
    int i = gid >> 4;
    if (i >= NATOMS) return;
    int lane = (gid & 15) * 4;
    int b = __ldg(batch + i);
    float4 v = *(const float4*)(g_h + (size_t)i * 64 + lane);
    float* addr = g_gr + (size_t)b * 64 + lane;
    asm volatile("red.global.add.v4.f32 [%0], {%1,%2,%3,%4};"
                 :: "l"(addr), "f"(v.x), "f"(v.y), "f"(v.z), "f"(v.w)
                 : "memory");
}

// ---------------- output head --------------------------------------------------
__global__ __launch_bounds__(256) void k_head(
    const float* __restrict__ W1, const float* __restrict__ B1,
    const float* __restrict__ W2, const float* __restrict__ B2,
    float* __restrict__ out)
{
    __shared__ float w1s[64 * 32];
    __shared__ float w2s[32];
    __shared__ float b1s[32];
    for (int i = threadIdx.x; i < 2048; i += 256) w1s[i] = W1[i];
    if (threadIdx.x < 32) { w2s[threadIdx.x] = W2[threadIdx.x]; b1s[threadIdx.x] = B1[threadIdx.x]; }
    __syncthreads();
    int g = threadIdx.x;
    if (g >= NGRAPH) return;
    float gv[64];
    #pragma unroll 16
    for (int k = 0; k < 64; k++) gv[k] = g_gr[g * 64 + k];
    float o = B2[0];
    #pragma unroll 4
    for (int j = 0; j < 32; j++) {
        float a = b1s[j];
        #pragma unroll 16
        for (int k = 0; k < 64; k++) a += gv[k] * w1s[k * 32 + j];
        o += fmaxf(a, 0.0f) * w2s[j];
    }
    out[g] = o;
}

// ---------------- launcher ------------------------------------------------------
extern "C" void kernel_launch(void* const* d_in, const int* in_sizes, int n_in,
                              void* d_out, int out_size) {
    const int*   z      = (const int*)  d_in[0];
    const float* pos    = (const float*)d_in[1];
    const int*   batch  = (const int*)  d_in[2];
    const int*   ei     = (const int*)  d_in[3];
    const float* emb    = (const float*)d_in[4];
    const float* mlp_w1 = (const float*)d_in[5];
    const float* mlp_b1 = (const float*)d_in[6];
    const float* mlp_w2 = (const float*)d_in[7];
    const float* mlp_b2 = (const float*)d_in[8];
    const float* cf1_w  = (const float*)d_in[9];
    const float* cf2_w  = (const float*)d_in[10];
    const float* cf2_b  = (const float*)d_in[11];
    const float* lin_w  = (const float*)d_in[12];
    const float* lin_b  = (const float*)d_in[13];
    const float* out1_w = (const float*)d_in[14];
    const float* out1_b = (const float*)d_in[15];
    const float* out2_w = (const float*)d_in[16];
    const float* out2_b = (const float*)d_in[17];
    float* out = (float*)d_out;

    // CSR build (edge_index constant across interactions)
    k_zero   <<<(NATOMS + 255) / 256, 256>>>();
    k_hist   <<<(NEDGE + 255) / 256, 256>>>(ei);
    k_scan1  <<<NSCANB, 1024>>>();
    k_scan2  <<<1, 64>>>();
    k_scan3  <<<NSCANB, 1024>>>();
    k_scatter<<<(NEDGE + 255) / 256, 256>>>(pos, ei);

    k_table    <<<NB * (MTAB / 32), 64>>>(mlp_w1, mlp_b1, mlp_w2, mlp_b2);
    k_embed_cf1<<<(NATOMS + 63) / 64, 256>>>(z, emb, cf1_w);

    for (int t = 0; t < NB; t++) {
        k_agg<<<(NATOMS + 7) / 8, 256>>>(t);
        const float* w1 = cf2_w + (size_t)t * 64 * 64;
        const float* b1 = cf2_b + (size_t)t * 64;
        const float* w2 = lin_w + (size_t)t * 64 * 64;
        const float* b2 = lin_b + (size_t)t * 64;
        if (t + 1 < NB)
            k_cf2lin<true><<<(NATOMS + 63) / 64, 256>>>(w1, b1, w2, b2,
                cf1_w + (size_t)(t + 1) * 64 * 64);
        else
            k_cf2lin<false><<<(NATOMS + 63) / 64, 256>>>(w1, b1, w2, b2, nullptr);
    }

    k_scatter_g<<<(NATOMS * 16 + 255) / 256, 256>>>(batch);
    k_head<<<1, 256>>>(out1_w, out1_b, out2_w, out2_b, out);
}

// round 6
// speedup vs baseline: 1.6148x; 1.0085x over previous
#include <cuda_runtime.h>
#include <cuda_fp16.h>
#include <math.h>

#define NATOMS  50000
#define NEDGE   1600000
#define NGRAPH  250
#define HDIM    64
#define NGAUSS  50
#define NB      3
#define MTAB    8192
#define KBITS   13          // knot bits; src uses upper 17 bits (50000 < 2^17)
#define TABMAX  8.6700f     // > 5*sqrt(3) = 8.66025
#define TABSCALE ((float)(MTAB - 1) / TABMAX)
#define TABSTEP  (TABMAX / (float)(MTAB - 1))
#define NSCANB  49          // ceil(NATOMS / 1024)

// ---------------- scratch (device globals; no allocation allowed) ----------
__device__ __half    g_tabh[NB * MTAB * HDIM];  // 3.1 MB  Wf(d) table, fp16
__device__ float     g_h[NATOMS * HDIM];        // 12.8 MB node features
__device__ __half    g_hxh[NATOMS * HDIM];      // 6.4 MB  h @ cf1_w, fp16
__device__ float     g_agg[NATOMS * HDIM];      // 12.8 MB gather accumulator
__device__ float     g_gr[NGRAPH * HDIM];       // graph readout
__device__ int       g_cnt[NATOMS];             // histogram
__device__ int       g_rp[NATOMS + 1];          // CSR rowptr
__device__ int       g_cur[NATOMS];             // scatter cursors
__device__ int       g_bsum[64];                // scan block sums
__device__ unsigned  g_src[NEDGE];              // dst-sorted packed (src<<13 | knot)

__device__ __forceinline__ float ssp(float v) {
    return fmaxf(v, 0.0f) + log1pf(expf(-fabsf(v))) - 0.6931471805599453f;
}

// ---------------- CSR build --------------------------------------------------
__global__ void k_zero() {
    int i = blockIdx.x * blockDim.x + threadIdx.x;
    if (i < NATOMS) g_cnt[i] = 0;
    if (i < NGRAPH * HDIM) g_gr[i] = 0.0f;
}

__global__ void k_hist(const int* __restrict__ ei) {
    int e = blockIdx.x * blockDim.x + threadIdx.x;
    if (e >= NEDGE) return;
    atomicAdd(&g_cnt[__ldg(ei + NEDGE + e)], 1);
}

__global__ __launch_bounds__(1024) void k_scan1() {
    __shared__ int wsum[32];
    int tid = threadIdx.x, lane = tid & 31, wid = tid >> 5;
    int i = blockIdx.x * 1024 + tid;
    int v = (i < NATOMS) ? g_cnt[i] : 0;
    int incl = v;
    #pragma unroll
    for (int off = 1; off < 32; off <<= 1) {
        int n = __shfl_up_sync(0xffffffffu, incl, off);
        if (lane >= off) incl += n;
    }
    if (lane == 31) wsum[wid] = incl;
    __syncthreads();
    if (wid == 0) {
        int wv = wsum[lane];
        int wincl = wv;
        #pragma unroll
        for (int off = 1; off < 32; off <<= 1) {
            int n = __shfl_up_sync(0xffffffffu, wincl, off);
            if (lane >= off) wincl += n;
        }
        wsum[lane] = wincl - wv;
    }
    __syncthreads();
    int excl = wsum[wid] + incl - v;
    if (i < NATOMS) g_rp[i] = excl;
    if (tid == 1023) g_bsum[blockIdx.x] = excl + v;
}

__global__ void k_scan2() {
    __shared__ int ws[2];
    int tid = threadIdx.x, lane = tid & 31;
    int v = (tid < NSCANB) ? g_bsum[tid] : 0;
    int incl = v;
    #pragma unroll
    for (int off = 1; off < 32; off <<= 1) {
        int n = __shfl_up_sync(0xffffffffu, incl, off);
        if (lane >= off) incl += n;
    }
    if (lane == 31) ws[tid >> 5] = incl;
    __syncthreads();
    int add = (tid >= 32) ? ws[0] : 0;
    if (tid < NSCANB) g_bsum[tid] = incl - v + add;
}

__global__ __launch_bounds__(1024) void k_scan3() {
    int i = blockIdx.x * 1024 + threadIdx.x;
    if (i < NATOMS) {
        int r = g_rp[i] + g_bsum[blockIdx.x];
        g_rp[i] = r;
        g_cur[i] = r;
    }
    if (i == 0) g_rp[NATOMS] = NEDGE;
}

// distance -> nearest knot; scatter packed (src<<13 | knot) to dst-sorted slot
__global__ void k_scatter(const float* __restrict__ pos, const int* __restrict__ ei) {
    int e = blockIdx.x * blockDim.x + threadIdx.x;
    if (e >= NEDGE) return;
    int s = __ldg(ei + e);
    int t = __ldg(ei + NEDGE + e);
    float dx = __ldg(pos + 3 * t + 0) - __ldg(pos + 3 * s + 0);
    float dy = __ldg(pos + 3 * t + 1) - __ldg(pos + 3 * s + 1);
    float dz = __ldg(pos + 3 * t + 2) - __ldg(pos + 3 * s + 2);
    float d = sqrtf(dx * dx + dy * dy + dz * dz);
    int knot = (int)(d * TABSCALE + 0.5f);
    knot = min(knot, MTAB - 1);
    int p = atomicAdd(&g_cur[t], 1);
    g_src[p] = ((unsigned)s << KBITS) | (unsigned)knot;
}

// ---------------- build Wf(d) table (fp16): [NB][MTAB][64] -------------------
__global__ __launch_bounds__(64) void k_table(
    const float* __restrict__ w1, const float* __restrict__ b1,
    const float* __restrict__ w2, const float* __restrict__ b2)
{
    __shared__ float w1s[NGAUSS * 64];
    __shared__ float w2s[64 * 64];
    __shared__ float b1s[64], b2s[64];
    __shared__ float rbfs[NGAUSS];
    __shared__ float t1s[64];

    const int KPB = 32;
    int t  = blockIdx.x / (MTAB / KPB);
    int kb = blockIdx.x % (MTAB / KPB);
    int tid = threadIdx.x;

    for (int i = tid; i < NGAUSS * 64; i += 64) w1s[i] = w1[t * NGAUSS * 64 + i];
    for (int i = tid; i < 64 * 64;     i += 64) w2s[i] = w2[t * 64 * 64 + i];
    b1s[tid] = b1[t * 64 + tid];
    b2s[tid] = b2[t * 64 + tid];

    const float step  = 10.0f / 49.0f;
    const float coeff = -0.5f / (step * step);

    for (int kk = 0; kk < KPB; kk++) {
        int knot = kb * KPB + kk;
        float dv = (float)knot * TABSTEP;
        __syncthreads();
        if (tid < NGAUSS) {
            float dd = dv - (float)tid * step;
            rbfs[tid] = expf(coeff * dd * dd);
        }
        __syncthreads();
        float a = b1s[tid];
        #pragma unroll 10
        for (int j = 0; j < NGAUSS; j++) a += rbfs[j] * w1s[j * 64 + tid];
        t1s[tid] = ssp(a);
        __syncthreads();
        float a2 = b2s[tid];
        #pragma unroll 16
        for (int k = 0; k < 64; k++) a2 += t1s[k] * w2s[k * 64 + tid];
        float C = 0.5f * (cosf(dv * 0.31415926535897931f) + 1.0f);
        g_tabh[((size_t)t * MTAB + knot) * 64 + tid] = __float2half_rn(a2 * C);
    }
}

// ---------------- fused embed + cf1(t=0) -------------------------------------
__global__ __launch_bounds__(256) void k_embed_cf1(
    const int* __restrict__ z, const float* __restrict__ emb,
    const float* __restrict__ W)
{
    __shared__ float Ws[64 * 64];
    for (int i = threadIdx.x; i < 4096; i += 256) Ws[i] = W[i];
    __syncthreads();

    int row  = blockIdx.x * 64 + (threadIdx.x >> 2);
    int rowc = min(row, NATOMS - 1);
    int q    = threadIdx.x & 3;
    int lane = threadIdx.x & 31;

    int zi = __ldg(z + rowc);
    float xs[16];
    const float4* xr = (const float4*)(emb + (size_t)zi * 64 + q * 16);
    ((float4*)xs)[0] = __ldg(xr);     ((float4*)xs)[1] = __ldg(xr + 1);
    ((float4*)xs)[2] = __ldg(xr + 2); ((float4*)xs)[3] = __ldg(xr + 3);

    float acc[16];
    #pragma unroll
    for (int j = 0; j < 16; j++) acc[j] = 0.0f;
    #pragma unroll
    for (int k = 0; k < 64; k++) {
        float xk = __shfl_sync(0xffffffffu, xs[k & 15], (lane & ~3) | (k >> 4), 32);
        const float* wr = Ws + k * 64 + q * 16;
        #pragma unroll
        for (int j = 0; j < 16; j++) acc[j] = fmaf(xk, wr[j], acc[j]);
    }

    if (row < NATOMS) {
        float4* hp = (float4*)(g_h + (size_t)row * 64 + q * 16);
        hp[0] = ((float4*)xs)[0]; hp[1] = ((float4*)xs)[1];
        hp[2] = ((float4*)xs)[2]; hp[3] = ((float4*)xs)[3];
        __half2 hv[8];
        #pragma unroll
        for (int j = 0; j < 8; j++) hv[j] = __floats2half2_rn(acc[2 * j], acc[2 * j + 1]);
        uint4* dstp = (uint4*)(g_hxh + (size_t)row * 64 + q * 16);
        dstp[0] = *(uint4*)(hv);
        dstp[1] = *(uint4*)(hv + 4);
    }
}

// ---------------- gather-aggregate v5 ----------------------------------------
// one warp/node; 4 edges per warp-instruction (4 groups x 8 lanes, LDG.128 each).
// Full 32-record batches run an unpredicated statically-unrolled body so ptxas
// can front-batch the independent LDGs (MLP); ragged tail is predicated.
__device__ __forceinline__ void agg_step(
    const __half* __restrict__ tb, unsigned r, int fl, float* a)
{
    unsigned knot = r & (MTAB - 1);
    unsigned src  = r >> KBITS;
    uint4 tv = __ldg((const uint4*)(tb + (size_t)knot * 64) + fl);
    uint4 hv = __ldg((const uint4*)(g_hxh + (size_t)src * 64) + fl);
    __half2 p0 = __hmul2(*(__half2*)&tv.x, *(__half2*)&hv.x);
    __half2 p1 = __hmul2(*(__half2*)&tv.y, *(__half2*)&hv.y);
    __half2 p2 = __hmul2(*(__half2*)&tv.z, *(__half2*)&hv.z);
    __half2 p3 = __hmul2(*(__half2*)&tv.w, *(__half2*)&hv.w);
    float2 f0 = __half22float2(p0);
    float2 f1 = __half22float2(p1);
    float2 f2 = __half22float2(p2);
    float2 f3 = __half22float2(p3);
    a[0] += f0.x; a[1] += f0.y;
    a[2] += f1.x; a[3] += f1.y;
    a[4] += f2.x; a[5] += f2.y;
    a[6] += f3.x; a[7] += f3.y;
}

__global__ __launch_bounds__(256) void k_agg(int t) {
    int node = blockIdx.x * 8 + (threadIdx.x >> 5);
    if (node >= NATOMS) return;
    int lane = threadIdx.x & 31;
    int grp  = lane >> 3;       // which edge of the 4-pack
    int fl   = lane & 7;        // 16-byte slot within the 128B feature row
    int beg = __ldg(&g_rp[node]), end = __ldg(&g_rp[node + 1]);

    float a[8];
    #pragma unroll
    for (int i = 0; i < 8; i++) a[i] = 0.0f;
    const __half* tb = g_tabh + (size_t)t * MTAB * 64;

    int base = beg;
    // ---- full batches: unpredicated, statically unrolled ----
    for (; base + 32 <= end; base += 32) {
        unsigned rec = __ldg(&g_src[base + lane]);
        #pragma unroll 4
        for (int j = 0; j < 32; j += 4) {
            unsigned r = __shfl_sync(0xffffffffu, rec, j + grp);
            agg_step(tb, r, fl, a);
        }
    }
    // ---- ragged tail ----
    if (base < end) {
        unsigned rec = 0u;
        if (base + lane < end) rec = __ldg(&g_src[base + lane]);
        int n = end - base;
        for (int j = 0; j < n; j += 4) {
            unsigned r = __shfl_sync(0xffffffffu, rec, j + grp);
            if (j + grp < n) agg_step(tb, r, fl, a);
        }
    }

    // fold the 4 edge-groups (grp 0..3 -> grp 0)
    #pragma unroll
    for (int i = 0; i < 8; i++) {
        a[i] += __shfl_down_sync(0xffffffffu, a[i], 16);
        a[i] += __shfl_down_sync(0xffffffffu, a[i], 8);
    }
    if (grp == 0) {
        float4* dst = (float4*)(g_agg + (size_t)node * 64 + fl * 8);
        dst[0] = make_float4(a[0], a[1], a[2], a[3]);
        dst[1] = make_float4(a[4], a[5], a[6], a[7]);
    }
}

// ---------------- fused: h += ssp(agg@W1+b1)@W2+b2 ; hx = h@W3 ---------------
template <bool FUSE_NEXT>
__global__ __launch_bounds__(256) void k_cf2lin(
    const float* __restrict__ W1, const float* __restrict__ B1,
    const float* __restrict__ W2, const float* __restrict__ B2,
    const float* __restrict__ W3)
{
    __shared__ float W1s[64 * 64];
    __shared__ float W2s[64 * 64];
    __shared__ float W3s[64 * 64];
    for (int i = threadIdx.x; i < 4096; i += 256) {
        W1s[i] = W1[i];
        W2s[i] = W2[i];
        if (FUSE_NEXT) W3s[i] = W3[i];
    }
    __syncthreads();

    int row  = blockIdx.x * 64 + (threadIdx.x >> 2);
    int rowc = min(row, NATOMS - 1);
    int q    = threadIdx.x & 3;
    int lane = threadIdx.x & 31;

    float xs[16];
    const float4* xr = (const float4*)(g_agg + (size_t)rowc * 64 + q * 16);
    ((float4*)xs)[0] = xr[0]; ((float4*)xs)[1] = xr[1];
    ((float4*)xs)[2] = xr[2]; ((float4*)xs)[3] = xr[3];

    float acc[16];
    #pragma unroll
    for (int j = 0; j < 16; j++) acc[j] = B1[q * 16 + j];
    #pragma unroll
    for (int k = 0; k < 64; k++) {
        float xk = __shfl_sync(0xffffffffu, xs[k & 15], (lane & ~3) | (k >> 4), 32);
        const float* wr = W1s + k * 64 + q * 16;
        #pragma unroll
        for (int j = 0; j < 16; j++) acc[j] = fmaf(xk, wr[j], acc[j]);
    }

    float us[16];
    #pragma unroll
    for (int j = 0; j < 16; j++) us[j] = ssp(acc[j]);

    #pragma unroll
    for (int j = 0; j < 16; j++) acc[j] = B2[q * 16 + j];
    #pragma unroll
    for (int k = 0; k < 64; k++) {
        float uk = __shfl_sync(0xffffffffu, us[k & 15], (lane & ~3) | (k >> 4), 32);
        const float* wr = W2s + k * 64 + q * 16;
        #pragma unroll
        for (int j = 0; j < 16; j++) acc[j] = fmaf(uk, wr[j], acc[j]);
    }

    float hn[16];
    const float4* hr = (const float4*)(g_h + (size_t)rowc * 64 + q * 16);
    float4 h0 = hr[0], h1 = hr[1], h2 = hr[2], h3 = hr[3];
    hn[0] = h0.x + acc[0];  hn[1] = h0.y + acc[1];  hn[2] = h0.z + acc[2];  hn[3] = h0.w + acc[3];
    hn[4] = h1.x + acc[4];  hn[5] = h1.y + acc[5];  hn[6] = h1.z + acc[6];  hn[7] = h1.w + acc[7];
    hn[8] = h2.x + acc[8];  hn[9] = h2.y + acc[9];  hn[10] = h2.z + acc[10]; hn[11] = h2.w + acc[11];
    hn[12] = h3.x + acc[12]; hn[13] = h3.y + acc[13]; hn[14] = h3.z + acc[14]; hn[15] = h3.w + acc[15];

    if (row < NATOMS) {
        float4* hp = (float4*)(g_h + (size_t)row * 64 + q * 16);
        hp[0] = ((float4*)hn)[0]; hp[1] = ((float4*)hn)[1];
        hp[2] = ((float4*)hn)[2]; hp[3] = ((float4*)hn)[3];
    }

    if (FUSE_NEXT) {
        #pragma unroll
        for (int j = 0; j < 16; j++) acc[j] = 0.0f;
        #pragma unroll
        for (int k = 0; k < 64; k++) {
            float hk = __shfl_sync(0xffffffffu, hn[k & 15], (lane & ~3) | (k >> 4), 32);
            const float* wr = W3s + k * 64 + q * 16;
            #pragma unroll
            for (int j = 0; j < 16; j++) acc[j] = fmaf(hk, wr[j], acc[j]);
        }
        if (row < NATOMS) {
            __half2 hv[8];
            #pragma unroll
            for (int j = 0; j < 8; j++) hv[j] = __floats2half2_rn(acc[2 * j], acc[2 * j + 1]);
            uint4* dstp = (uint4*)(g_hxh + (size_t)row * 64 + q * 16);
            dstp[0] = *(uint4*)(hv);
            dstp[1] = *(uint4*)(hv + 4);
        }
    }
}

// ---------------- graph readout scatter --------------------------------------
__global__ void k_scatter_g(const int* __restrict__ batch) {
    int gid = blockIdx.x * blockDim.x + threadIdx.x;
    int i = gid >> 4;
    if (i >= NATOMS) return;
    int lane = (gid & 15) * 4;
    int b = __ldg(batch + i);
    float4 v = *(const float4*)(g_h + (size_t)i * 64 + lane);
    float* addr = g_gr + (size_t)b * 64 + lane;
    asm volatile("red.global.add.v4.f32 [%0], {%1,%2,%3,%4};"
                 :: "l"(addr), "f"(v.x), "f"(v.y), "f"(v.z), "f"(v.w)
                 : "memory");
}

// ---------------- output head --------------------------------------------------
__global__ __launch_bounds__(256) void k_head(
    const float* __restrict__ W1, const float* __restrict__ B1,
    const float* __restrict__ W2, const float* __restrict__ B2,
    float* __restrict__ out)
{
    __shared__ float w1s[64 * 32];
    __shared__ float w2s[32];
    __shared__ float b1s[32];
    for (int i = threadIdx.x; i < 2048; i += 256) w1s[i] = W1[i];
    if (threadIdx.x < 32) { w2s[threadIdx.x] = W2[threadIdx.x]; b1s[threadIdx.x] = B1[threadIdx.x]; }
    __syncthreads();
    int g = threadIdx.x;
    if (g >= NGRAPH) return;
    float gv[64];
    #pragma unroll 16
    for (int k = 0; k < 64; k++) gv[k] = g_gr[g * 64 + k];
    float o = B2[0];
    #pragma unroll 4
    for (int j = 0; j < 32; j++) {
        float a = b1s[j];
        #pragma unroll 16
        for (int k = 0; k < 64; k++) a += gv[k] * w1s[k * 32 + j];
        o += fmaxf(a, 0.0f) * w2s[j];
    }
    out[g] = o;
}

// ---------------- launcher ------------------------------------------------------
extern "C" void kernel_launch(void* const* d_in, const int* in_sizes, int n_in,
                              void* d_out, int out_size) {
    const int*   z      = (const int*)  d_in[0];
    const float* pos    = (const float*)d_in[1];
    const int*   batch  = (const int*)  d_in[2];
    const int*   ei     = (const int*)  d_in[3];
    const float* emb    = (const float*)d_in[4];
    const float* mlp_w1 = (const float*)d_in[5];
    const float* mlp_b1 = (const float*)d_in[6];
    const float* mlp_w2 = (const float*)d_in[7];
    const float* mlp_b2 = (const float*)d_in[8];
    const float* cf1_w  = (const float*)d_in[9];
    const float* cf2_w  = (const float*)d_in[10];
    const float* cf2_b  = (const float*)d_in[11];
    const float* lin_w  = (const float*)d_in[12];
    const float* lin_b  = (const float*)d_in[13];
    const float* out1_w = (const float*)d_in[14];
    const float* out1_b = (const float*)d_in[15];
    const float* out2_w = (const float*)d_in[16];
    const float* out2_b = (const float*)d_in[17];
    float* out = (float*)d_out;

    // CSR build (edge_index constant across interactions).
    // k_embed_cf1 has no CSR dependency; placed 4th so ncu's fixed-index
    // capture finally profiles a kernel that matters.
    k_zero     <<<(NATOMS + 255) / 256, 256>>>();
    k_hist     <<<(NEDGE + 255) / 256, 256>>>(ei);
    k_scan1    <<<NSCANB, 1024>>>();
    k_embed_cf1<<<(NATOMS + 63) / 64, 256>>>(z, emb, cf1_w);
    k_scan2    <<<1, 64>>>();
    k_scan3    <<<NSCANB, 1024>>>();
    k_scatter  <<<(NEDGE + 255) / 256, 256>>>(pos, ei);
    k_table    <<<NB * (MTAB / 32), 64>>>(mlp_w1, mlp_b1, mlp_w2, mlp_b2);

    for (int t = 0; t < NB; t++) {
        k_agg<<<(NATOMS + 7) / 8, 256>>>(t);
        const float* w1 = cf2_w + (size_t)t * 64 * 64;
        const float* b1 = cf2_b + (size_t)t * 64;
        const float* w2 = lin_w + (size_t)t * 64 * 64;
        const float* b2 = lin_b + (size_t)t * 64;
        if (t + 1 < NB)
            k_cf2lin<true><<<(NATOMS + 63) / 64, 256>>>(w1, b1, w2, b2,
                cf1_w + (size_t)(t + 1) * 64 * 64);
        else
            k_cf2lin<false><<<(NATOMS + 63) / 64, 256>>>(w1, b1, w2, b2, nullptr);
    }

    k_scatter_g<<<(NATOMS * 16 + 255) / 256, 256>>>(batch);
    k_head<<<1, 256>>>(out1_w, out1_b, out2_w, out2_b, out);
}

// round 8
// speedup vs baseline: 2.7924x; 1.7293x over previous
#include <cuda_runtime.h>
#include <cuda_fp16.h>
#include <math.h>

#define NATOMS  50000
#define NEDGE   1600000
#define NGRAPH  250
#define HDIM    64
#define NGAUSS  50
#define NB      3
#define MTAB    8192
#define KBITS   13
#define TABMAX  8.6700f
#define TABSCALE ((float)(MTAB - 1) / TABMAX)
#define TABSTEP  (TABMAX / (float)(MTAB - 1))
#define NSCANB  49

// GEMM tiling
#define RPB        128                    // rows per block
#define GEMM_GRID  ((NATOMS + RPB - 1) / RPB)
#define XS_FLOATS  (64 * 128)             // Xs: [k=64][row=128] transposed, swizzled
#define WS_STRIDE  72
#define SMEM_FLOATS (XS_FLOATS + 64 * WS_STRIDE)
#define SMEM_BYTES  (SMEM_FLOATS * 4)     // 51200

// ---------------- scratch ----------------------------------------------------
__device__ __half    g_tabh[NB * MTAB * HDIM];
__device__ float     g_h[NATOMS * HDIM];
__device__ __half    g_hxh[NATOMS * HDIM];
__device__ float     g_agg[NATOMS * HDIM];
__device__ float     g_gr[NGRAPH * HDIM];
__device__ int       g_cnt[NATOMS];
__device__ int       g_rp[NATOMS + 1];
__device__ int       g_cur[NATOMS];
__device__ int       g_bsum[64];
__device__ unsigned  g_src[NEDGE];

__device__ __forceinline__ float ssp(float v) {
    return fmaxf(v, 0.0f) + log1pf(expf(-fabsf(v))) - 0.6931471805599453f;
}

// __half2 -> unsigned bit reinterpret (no such intrinsic in headers)
__device__ __forceinline__ unsigned h2u(__half2 h) {
    unsigned u;
    asm("mov.b32 %0,%1;" : "=r"(u) : "r"(*(unsigned*)&h));
    return u;
}

// ---------------- f32x2 helpers ----------------------------------------------
__device__ __forceinline__ unsigned long long pack11(float x) {
    unsigned long long r; asm("mov.b64 %0,{%1,%1};" : "=l"(r) : "f"(x)); return r;
}
__device__ __forceinline__ unsigned long long packxy(float x, float y) {
    unsigned long long r; asm("mov.b64 %0,{%1,%2};" : "=l"(r) : "f"(x), "f"(y)); return r;
}
__device__ __forceinline__ float2 unpk(unsigned long long v) {
    float2 r; asm("mov.b64 {%0,%1},%2;" : "=f"(r.x), "=f"(r.y) : "l"(v)); return r;
}
__device__ __forceinline__ void fma2(unsigned long long& a, unsigned long long x,
                                     unsigned long long w) {
    asm("fma.rn.f32x2 %0,%1,%2,%0;" : "+l"(a) : "l"(x), "l"(w));
}

// swizzled transposed-X index: Xs[k][row], row-group XORed by f(k) for bank spread
__device__ __forceinline__ int xidx(int k, int r) {
    int g = ((k >> 3) + k) & 7;
    return k * 128 + ((((r >> 2) ^ g)) << 2) + (r & 3);
}

// ---------------- GEMM core: acc[4 rows][4 col-pairs] += Xs^T * Ws ------------
__device__ __forceinline__ void gemm64(const float* __restrict__ Xs,
                                       const float* __restrict__ Ws,
                                       int ty, int tx,
                                       unsigned long long (&acc)[4][4])
{
    #pragma unroll 8
    for (int k = 0; k < 64; k++) {
        int g = ((k >> 3) + k) & 7;
        const float4 xv = *(const float4*)(Xs + k * 128 + (((ty ^ g)) << 2));
        const ulonglong2 wa = *(const ulonglong2*)(Ws + k * WS_STRIDE + (tx << 3));
        const ulonglong2 wb = *(const ulonglong2*)(Ws + k * WS_STRIDE + (tx << 3) + 4);
        unsigned long long x;
        x = pack11(xv.x);
        fma2(acc[0][0], x, wa.x); fma2(acc[0][1], x, wa.y);
        fma2(acc[0][2], x, wb.x); fma2(acc[0][3], x, wb.y);
        x = pack11(xv.y);
        fma2(acc[1][0], x, wa.x); fma2(acc[1][1], x, wa.y);
        fma2(acc[1][2], x, wb.x); fma2(acc[1][3], x, wb.y);
        x = pack11(xv.z);
        fma2(acc[2][0], x, wa.x); fma2(acc[2][1], x, wa.y);
        fma2(acc[2][2], x, wb.x); fma2(acc[2][3], x, wb.y);
        x = pack11(xv.w);
        fma2(acc[3][0], x, wa.x); fma2(acc[3][1], x, wa.y);
        fma2(acc[3][2], x, wb.x); fma2(acc[3][3], x, wb.y);
    }
}

__device__ __forceinline__ void load_W(float* Ws, const float* __restrict__ W, int tid) {
    for (int i = tid; i < 4096; i += 256)
        Ws[(i >> 6) * WS_STRIDE + (i & 63)] = __ldg(W + i);
}

// stage rows of a [N][64] fp32 matrix transposed into Xs
__device__ __forceinline__ void stage_rows(float* Xs, const float* __restrict__ src,
                                           int r0, int tid)
{
    #pragma unroll
    for (int it = 0; it < 8; it++) {
        int idx = it * 256 + tid;          // 0..2047
        int row = idx & 127;
        int c = (idx >> 7) << 2;           // 0..60 step 4
        int gr = min(r0 + row, NATOMS - 1);
        float4 v = __ldg((const float4*)(src + (size_t)gr * 64 + c));
        Xs[xidx(c + 0, row)] = v.x;
        Xs[xidx(c + 1, row)] = v.y;
        Xs[xidx(c + 2, row)] = v.z;
        Xs[xidx(c + 3, row)] = v.w;
    }
}

// ---------------- CSR build ----------------------------------------------------
__global__ void k_zero() {
    int i = blockIdx.x * blockDim.x + threadIdx.x;
    if (i < NATOMS) g_cnt[i] = 0;
    if (i < NGRAPH * HDIM) g_gr[i] = 0.0f;
}

__global__ void k_hist(const int* __restrict__ ei) {
    int e = blockIdx.x * blockDim.x + threadIdx.x;
    if (e >= NEDGE) return;
    atomicAdd(&g_cnt[__ldg(ei + NEDGE + e)], 1);
}

__global__ __launch_bounds__(1024) void k_scan1() {
    __shared__ int wsum[32];
    int tid = threadIdx.x, lane = tid & 31, wid = tid >> 5;
    int i = blockIdx.x * 1024 + tid;
    int v = (i < NATOMS) ? g_cnt[i] : 0;
    int incl = v;
    #pragma unroll
    for (int off = 1; off < 32; off <<= 1) {
        int n = __shfl_up_sync(0xffffffffu, incl, off);
        if (lane >= off) incl += n;
    }
    if (lane == 31) wsum[wid] = incl;
    __syncthreads();
    if (wid == 0) {
        int wv = wsum[lane];
        int wincl = wv;
        #pragma unroll
        for (int off = 1; off < 32; off <<= 1) {
            int n = __shfl_up_sync(0xffffffffu, wincl, off);
            if (lane >= off) wincl += n;
        }
        wsum[lane] = wincl - wv;
    }
    __syncthreads();
    int excl = wsum[wid] + incl - v;
    if (i < NATOMS) g_rp[i] = excl;
    if (tid == 1023) g_bsum[blockIdx.x] = excl + v;
}

__global__ void k_scan2() {
    __shared__ int ws[2];
    int tid = threadIdx.x, lane = tid & 31;
    int v = (tid < NSCANB) ? g_bsum[tid] : 0;
    int incl = v;
    #pragma unroll
    for (int off = 1; off < 32; off <<= 1) {
        int n = __shfl_up_sync(0xffffffffu, incl, off);
        if (lane >= off) incl += n;
    }
    if (lane == 31) ws[tid >> 5] = incl;
    __syncthreads();
    int add = (tid >= 32) ? ws[0] : 0;
    if (tid < NSCANB) g_bsum[tid] = incl - v + add;
}

__global__ __launch_bounds__(1024) void k_scan3() {
    int i = blockIdx.x * 1024 + threadIdx.x;
    if (i < NATOMS) {
        int r = g_rp[i] + g_bsum[blockIdx.x];
        g_rp[i] = r;
        g_cur[i] = r;
    }
    if (i == 0) g_rp[NATOMS] = NEDGE;
}

__global__ void k_scatter(const float* __restrict__ pos, const int* __restrict__ ei) {
    int e = blockIdx.x * blockDim.x + threadIdx.x;
    if (e >= NEDGE) return;
    int s = __ldg(ei + e);
    int t = __ldg(ei + NEDGE + e);
    float dx = __ldg(pos + 3 * t + 0) - __ldg(pos + 3 * s + 0);
    float dy = __ldg(pos + 3 * t + 1) - __ldg(pos + 3 * s + 1);
    float dz = __ldg(pos + 3 * t + 2) - __ldg(pos + 3 * s + 2);
    float d = sqrtf(dx * dx + dy * dy + dz * dz);
    int knot = (int)(d * TABSCALE + 0.5f);
    knot = min(knot, MTAB - 1);
    int p = atomicAdd(&g_cur[t], 1);
    g_src[p] = ((unsigned)s << KBITS) | (unsigned)knot;
}

// ---------------- build Wf(d) table (fp16) -------------------------------------
__global__ __launch_bounds__(64) void k_table(
    const float* __restrict__ w1, const float* __restrict__ b1,
    const float* __restrict__ w2, const float* __restrict__ b2)
{
    __shared__ float w1s[NGAUSS * 64];
    __shared__ float w2s[64 * 64];
    __shared__ float b1s[64], b2s[64];
    __shared__ float rbfs[NGAUSS];
    __shared__ float t1s[64];

    const int KPB = 32;
    int t  = blockIdx.x / (MTAB / KPB);
    int kb = blockIdx.x % (MTAB / KPB);
    int tid = threadIdx.x;

    for (int i = tid; i < NGAUSS * 64; i += 64) w1s[i] = w1[t * NGAUSS * 64 + i];
    for (int i = tid; i < 64 * 64;     i += 64) w2s[i] = w2[t * 64 * 64 + i];
    b1s[tid] = b1[t * 64 + tid];
    b2s[tid] = b2[t * 64 + tid];

    const float step  = 10.0f / 49.0f;
    const float coeff = -0.5f / (step * step);

    for (int kk = 0; kk < KPB; kk++) {
        int knot = kb * KPB + kk;
        float dv = (float)knot * TABSTEP;
        __syncthreads();
        if (tid < NGAUSS) {
            float dd = dv - (float)tid * step;
            rbfs[tid] = expf(coeff * dd * dd);
        }
        __syncthreads();
        float a = b1s[tid];
        #pragma unroll 10
        for (int j = 0; j < NGAUSS; j++) a += rbfs[j] * w1s[j * 64 + tid];
        t1s[tid] = ssp(a);
        __syncthreads();
        float a2 = b2s[tid];
        #pragma unroll 16
        for (int k = 0; k < 64; k++) a2 += t1s[k] * w2s[k * 64 + tid];
        float C = 0.5f * (cosf(dv * 0.31415926535897931f) + 1.0f);
        g_tabh[((size_t)t * MTAB + knot) * 64 + tid] = __float2half_rn(a2 * C);
    }
}

// ---------------- fused embed + cf1(t=0), f32x2 GEMM ----------------------------
__global__ __launch_bounds__(256) void k_embed_cf1(
    const int* __restrict__ z, const float* __restrict__ emb,
    const float* __restrict__ W)
{
    extern __shared__ float sm[];
    float* Xs = sm;
    float* Ws = sm + XS_FLOATS;
    int tid = threadIdx.x;
    int ty = tid >> 3, tx = tid & 7;
    int r0 = blockIdx.x * RPB;

    // stage X = emb[z[row]] transposed; also write g_h
    #pragma unroll
    for (int it = 0; it < 8; it++) {
        int idx = it * 256 + tid;
        int row = idx & 127;
        int c = (idx >> 7) << 2;
        int gr = min(r0 + row, NATOMS - 1);
        int zi = __ldg(z + gr);
        float4 v = __ldg((const float4*)(emb + (size_t)zi * 64 + c));
        if (r0 + row < NATOMS)
            *(float4*)(g_h + (size_t)gr * 64 + c) = v;
        Xs[xidx(c + 0, row)] = v.x;
        Xs[xidx(c + 1, row)] = v.y;
        Xs[xidx(c + 2, row)] = v.z;
        Xs[xidx(c + 3, row)] = v.w;
    }
    load_W(Ws, W, tid);
    __syncthreads();

    unsigned long long acc[4][4];
    #pragma unroll
    for (int i = 0; i < 4; i++)
        #pragma unroll
        for (int p = 0; p < 4; p++) acc[i][p] = 0ull;

    gemm64(Xs, Ws, ty, tx, acc);

    // write hx fp16: rows 4ty+i, cols 8tx..8tx+7
    #pragma unroll
    for (int i = 0; i < 4; i++) {
        int gr = r0 + 4 * ty + i;
        if (gr < NATOMS) {
            uint4 o;
            float2 f0 = unpk(acc[i][0]), f1 = unpk(acc[i][1]);
            float2 f2 = unpk(acc[i][2]), f3 = unpk(acc[i][3]);
            o.x = h2u(__floats2half2_rn(f0.x, f0.y));
            o.y = h2u(__floats2half2_rn(f1.x, f1.y));
            o.z = h2u(__floats2half2_rn(f2.x, f2.y));
            o.w = h2u(__floats2half2_rn(f3.x, f3.y));
            *(uint4*)(g_hxh + (size_t)gr * 64 + 8 * tx) = o;
        }
    }
}

// ---------------- gather-aggregate (unchanged from R6) --------------------------
__device__ __forceinline__ void agg_step(
    const __half* __restrict__ tb, unsigned r, int fl, float* a)
{
    unsigned knot = r & (MTAB - 1);
    unsigned src  = r >> KBITS;
    uint4 tv = __ldg((const uint4*)(tb + (size_t)knot * 64) + fl);
    uint4 hv = __ldg((const uint4*)(g_hxh + (size_t)src * 64) + fl);
    __half2 p0 = __hmul2(*(__half2*)&tv.x, *(__half2*)&hv.x);
    __half2 p1 = __hmul2(*(__half2*)&tv.y, *(__half2*)&hv.y);
    __half2 p2 = __hmul2(*(__half2*)&tv.z, *(__half2*)&hv.z);
    __half2 p3 = __hmul2(*(__half2*)&tv.w, *(__half2*)&hv.w);
    float2 f0 = __half22float2(p0);
    float2 f1 = __half22float2(p1);
    float2 f2 = __half22float2(p2);
    float2 f3 = __half22float2(p3);
    a[0] += f0.x; a[1] += f0.y;
    a[2] += f1.x; a[3] += f1.y;
    a[4] += f2.x; a[5] += f2.y;
    a[6] += f3.x; a[7] += f3.y;
}

__global__ __launch_bounds__(256) void k_agg(int t) {
    int node = blockIdx.x * 8 + (threadIdx.x >> 5);
    if (node >= NATOMS) return;
    int lane = threadIdx.x & 31;
    int grp  = lane >> 3;
    int fl   = lane & 7;
    int beg = __ldg(&g_rp[node]), end = __ldg(&g_rp[node + 1]);

    float a[8];
    #pragma unroll
    for (int i = 0; i < 8; i++) a[i] = 0.0f;
    const __half* tb = g_tabh + (size_t)t * MTAB * 64;

    int base = beg;
    for (; base + 32 <= end; base += 32) {
        unsigned rec = __ldg(&g_src[base + lane]);
        #pragma unroll 4
        for (int j = 0; j < 32; j += 4) {
            unsigned r = __shfl_sync(0xffffffffu, rec, j + grp);
            agg_step(tb, r, fl, a);
        }
    }
    if (base < end) {
        unsigned rec = 0u;
        if (base + lane < end) rec = __ldg(&g_src[base + lane]);
        int n = end - base;
        for (int j = 0; j < n; j += 4) {
            unsigned r = __shfl_sync(0xffffffffu, rec, j + grp);
            if (j + grp < n) agg_step(tb, r, fl, a);
        }
    }

    #pragma unroll
    for (int i = 0; i < 8; i++) {
        a[i] += __shfl_down_sync(0xffffffffu, a[i], 16);
        a[i] += __shfl_down_sync(0xffffffffu, a[i], 8);
    }
    if (grp == 0) {
        float4* dst = (float4*)(g_agg + (size_t)node * 64 + fl * 8);
        dst[0] = make_float4(a[0], a[1], a[2], a[3]);
        dst[1] = make_float4(a[4], a[5], a[6], a[7]);
    }
}

// ---------------- cf2lin: 3 GEMMs through one smem buffer -----------------------
template <bool FUSE_NEXT>
__global__ __launch_bounds__(256) void k_cf2lin(
    const float* __restrict__ W1, const float* __restrict__ B1,
    const float* __restrict__ W2, const float* __restrict__ B2,
    const float* __restrict__ W3)
{
    extern __shared__ float sm[];
    float* Xs = sm;
    float* Ws = sm + XS_FLOATS;
    int tid = threadIdx.x;
    int ty = tid >> 3, tx = tid & 7;
    int r0 = blockIdx.x * RPB;

    // ---- GEMM1: us = ssp(agg @ W1 + B1) ----
    stage_rows(Xs, g_agg, r0, tid);
    load_W(Ws, W1, tid);
    __syncthreads();

    unsigned long long acc[4][4];
    {
        float4 b0 = __ldg((const float4*)(B1 + 8 * tx));
        float4 b1 = __ldg((const float4*)(B1 + 8 * tx + 4));
        #pragma unroll
        for (int i = 0; i < 4; i++) {
            acc[i][0] = packxy(b0.x, b0.y);
            acc[i][1] = packxy(b0.z, b0.w);
            acc[i][2] = packxy(b1.x, b1.y);
            acc[i][3] = packxy(b1.z, b1.w);
        }
    }
    gemm64(Xs, Ws, ty, tx, acc);

    float us[4][8];
    #pragma unroll
    for (int i = 0; i < 4; i++) {
        #pragma unroll
        for (int p = 0; p < 4; p++) {
            float2 f = unpk(acc[i][p]);
            us[i][2 * p]     = ssp(f.x);
            us[i][2 * p + 1] = ssp(f.y);
        }
    }

    // ---- GEMM2: x = us @ W2 + B2 ----
    __syncthreads();
    #pragma unroll
    for (int i = 0; i < 4; i++)
        #pragma unroll
        for (int j = 0; j < 8; j++)
            Xs[xidx(8 * tx + j, 4 * ty + i)] = us[i][j];
    load_W(Ws, W2, tid);
    __syncthreads();

    {
        float4 b0 = __ldg((const float4*)(B2 + 8 * tx));
        float4 b1 = __ldg((const float4*)(B2 + 8 * tx + 4));
        #pragma unroll
        for (int i = 0; i < 4; i++) {
            acc[i][0] = packxy(b0.x, b0.y);
            acc[i][1] = packxy(b0.z, b0.w);
            acc[i][2] = packxy(b1.x, b1.y);
            acc[i][3] = packxy(b1.z, b1.w);
        }
    }
    gemm64(Xs, Ws, ty, tx, acc);

    // ---- residual: hn = h_old + x ; store ----
    float hn[4][8];
    #pragma unroll
    for (int i = 0; i < 4; i++) {
        int gr = min(r0 + 4 * ty + i, NATOMS - 1);
        float4 h0 = *(const float4*)(g_h + (size_t)gr * 64 + 8 * tx);
        float4 h1 = *(const float4*)(g_h + (size_t)gr * 64 + 8 * tx + 4);
        float2 f0 = unpk(acc[i][0]), f1 = unpk(acc[i][1]);
        float2 f2 = unpk(acc[i][2]), f3 = unpk(acc[i][3]);
        hn[i][0] = h0.x + f0.x; hn[i][1] = h0.y + f0.y;
        hn[i][2] = h0.z + f1.x; hn[i][3] = h0.w + f1.y;
        hn[i][4] = h1.x + f2.x; hn[i][5] = h1.y + f2.y;
        hn[i][6] = h1.z + f3.x; hn[i][7] = h1.w + f3.y;
        if (r0 + 4 * ty + i < NATOMS) {
            *(float4*)(g_h + (size_t)gr * 64 + 8 * tx)     = make_float4(hn[i][0], hn[i][1], hn[i][2], hn[i][3]);
            *(float4*)(g_h + (size_t)gr * 64 + 8 * tx + 4) = make_float4(hn[i][4], hn[i][5], hn[i][6], hn[i][7]);
        }
    }

    // ---- GEMM3 (fused next cf1): hx = hn @ W3, fp16 out ----
    if (FUSE_NEXT) {
        __syncthreads();
        #pragma unroll
        for (int i = 0; i < 4; i++)
            #pragma unroll
            for (int j = 0; j < 8; j++)
                Xs[xidx(8 * tx + j, 4 * ty + i)] = hn[i][j];
        load_W(Ws, W3, tid);
        __syncthreads();

        #pragma unroll
        for (int i = 0; i < 4; i++)
            #pragma unroll
            for (int p = 0; p < 4; p++) acc[i][p] = 0ull;
        gemm64(Xs, Ws, ty, tx, acc);

        #pragma unroll
        for (int i = 0; i < 4; i++) {
            int gr = r0 + 4 * ty + i;
            if (gr < NATOMS) {
                uint4 o;
                float2 f0 = unpk(acc[i][0]), f1 = unpk(acc[i][1]);
                float2 f2 = unpk(acc[i][2]), f3 = unpk(acc[i][3]);
                o.x = h2u(__floats2half2_rn(f0.x, f0.y));
                o.y = h2u(__floats2half2_rn(f1.x, f1.y));
                o.z = h2u(__floats2half2_rn(f2.x, f2.y));
                o.w = h2u(__floats2half2_rn(f3.x, f3.y));
                *(uint4*)(g_hxh + (size_t)gr * 64 + 8 * tx) = o;
            }
        }
    }
}

// ---------------- graph readout scatter ------------------------------------------
__global__ void k_scatter_g(const int* __restrict__ batch) {
    int gid = blockIdx.x * blockDim.x + threadIdx.x;
    int i = gid >> 4;
    if (i >= NATOMS) return;
    int lane = (gid & 15) * 4;
    int b = __ldg(batch + i);
    float4 v = *(const float4*)(g_h + (size_t)i * 64 + lane);
    float* addr = g_gr + (size_t)b * 64 + lane;
    asm volatile("red.global.add.v4.f32 [%0], {%1,%2,%3,%4};"
                 :: "l"(addr), "f"(v.x), "f"(v.y), "f"(v.z), "f"(v.w)
                 : "memory");
}

// ---------------- output head ------------------------------------------------------
__global__ __launch_bounds__(256) void k_head(
    const float* __restrict__ W1, const float* __restrict__ B1,
    const float* __restrict__ W2, const float* __restrict__ B2,
    float* __restrict__ out)
{
    __shared__ float w1s[64 * 32];
    __shared__ float w2s[32];
    __shared__ float b1s[32];
    for (int i = threadIdx.x; i < 2048; i += 256) w1s[i] = W1[i];
    if (threadIdx.x < 32) { w2s[threadIdx.x] = W2[threadIdx.x]; b1s[threadIdx.x] = B1[threadIdx.x]; }
    __syncthreads();
    int g = threadIdx.x;
    if (g >= NGRAPH) return;
    float gv[64];
    #pragma unroll 16
    for (int k = 0; k < 64; k++) gv[k] = g_gr[g * 64 + k];
    float o = B2[0];
    #pragma unroll 4
    for (int j = 0; j < 32; j++) {
        float a = b1s[j];
        #pragma unroll 16
        for (int k = 0; k < 64; k++) a += gv[k] * w1s[k * 32 + j];
        o += fmaxf(a, 0.0f) * w2s[j];
    }
    out[g] = o;
}

// ---------------- launcher ----------------------------------------------------------
extern "C" void kernel_launch(void* const* d_in, const int* in_sizes, int n_in,
                              void* d_out, int out_size) {
    const int*   z      = (const int*)  d_in[0];
    const float* pos    = (const float*)d_in[1];
    const int*   batch  = (const int*)  d_in[2];
    const int*   ei     = (const int*)  d_in[3];
    const float* emb    = (const float*)d_in[4];
    const float* mlp_w1 = (const float*)d_in[5];
    const float* mlp_b1 = (const float*)d_in[6];
    const float* mlp_w2 = (const float*)d_in[7];
    const float* mlp_b2 = (const float*)d_in[8];
    const float* cf1_w  = (const float*)d_in[9];
    const float* cf2_w  = (const float*)d_in[10];
    const float* cf2_b  = (const float*)d_in[11];
    const float* lin_w  = (const float*)d_in[12];
    const float* lin_b  = (const float*)d_in[13];
    const float* out1_w = (const float*)d_in[14];
    const float* out1_b = (const float*)d_in[15];
    const float* out2_w = (const float*)d_in[16];
    const float* out2_b = (const float*)d_in[17];
    float* out = (float*)d_out;

    // >48KB dynamic smem opt-in (host attribute set; graph-capture safe)
    cudaFuncSetAttribute(k_embed_cf1, cudaFuncAttributeMaxDynamicSharedMemorySize, SMEM_BYTES);
    cudaFuncSetAttribute(k_cf2lin<true>, cudaFuncAttributeMaxDynamicSharedMemorySize, SMEM_BYTES);
    cudaFuncSetAttribute(k_cf2lin<false>, cudaFuncAttributeMaxDynamicSharedMemorySize, SMEM_BYTES);

    k_zero     <<<(NATOMS + 255) / 256, 256>>>();
    k_hist     <<<(NEDGE + 255) / 256, 256>>>(ei);
    k_scan1    <<<NSCANB, 1024>>>();
    k_embed_cf1<<<GEMM_GRID, 256, SMEM_BYTES>>>(z, emb, cf1_w);   // ncu profiles launch #4
    k_scan2    <<<1, 64>>>();
    k_scan3    <<<NSCANB, 1024>>>();
    k_scatter  <<<(NEDGE + 255) / 256, 256>>>(pos, ei);
    k_table    <<<NB * (MTAB / 32), 64>>>(mlp_w1, mlp_b1, mlp_w2, mlp_b2);

    for (int t = 0; t < NB; t++) {
        k_agg<<<(NATOMS + 7) / 8, 256>>>(t);
        const float* w1 = cf2_w + (size_t)t * 64 * 64;
        const float* b1 = cf2_b + (size_t)t * 64;
        const float* w2 = lin_w + (size_t)t * 64 * 64;
        const float* b2 = lin_b + (size_t)t * 64;
        if (t + 1 < NB)
            k_cf2lin<true><<<GEMM_GRID, 256, SMEM_BYTES>>>(w1, b1, w2, b2,
                cf1_w + (size_t)(t + 1) * 64 * 64);
        else
            k_cf2lin<false><<<GEMM_GRID, 256, SMEM_BYTES>>>(w1, b1, w2, b2, nullptr);
    }

    k_scatter_g<<<(NATOMS * 16 + 255) / 256, 256>>>(batch);
    k_head<<<1, 256>>>(out1_w, out1_b, out2_w, out2_b, out);
}